// round 11
// baseline (speedup 1.0000x reference)
#include <cuda_runtime.h>
#include <cuda_fp16.h>
#include <cstdint>
#include <math.h>

#define NB     8
#define NS     4096
#define ND     1280
#define NCTX   77
#define NKP    80          // padded keys
#define NCDIM  2048
#define NADIM  768
#define NHEADS 20
#define NHD    64
#define MQ     (NB*NS)     // 32768
#define MKV    616
#define MKV_PAD 640

// ---------------- scratch (device globals; no allocation allowed) -----------
__device__ __half g_hs_h[MQ * ND];           // fp16(hidden_states)
__device__ __half g_q[MQ * ND];              // Q projection (fp16)
__device__ __half g_attn[MQ * ND];           // attention out (fp16)
__device__ __half g_enc_h[MKV_PAD * NCDIM];  // fp16(encoder), padded rows
__device__ __half g_k[MKV * ND];             // K fp16 (0.125 folded into wkt)
__device__ __half g_v[MKV * ND];
__device__ __half g_wqt[ND * ND];            // W^T fp16  [N,K]
__device__ __half g_wot[ND * ND];
__device__ __half g_wkt[ND * NCDIM];         // includes 0.125 scale
__device__ __half g_wvt[ND * NCDIM];
__device__ float  g_tip[NB * ND];
__device__ float  g_bias[NB * ND];

__device__ __forceinline__ void mma_f16(float* d, const uint32_t* a, const uint32_t* b) {
    asm volatile("mma.sync.aligned.m16n8k16.row.col.f32.f16.f16.f32 "
                 "{%0,%1,%2,%3}, {%4,%5,%6,%7}, {%8,%9}, {%0,%1,%2,%3};"
                 : "+f"(d[0]), "+f"(d[1]), "+f"(d[2]), "+f"(d[3])
                 : "r"(a[0]), "r"(a[1]), "r"(a[2]), "r"(a[3]),
                   "r"(b[0]), "r"(b[1]));
}
__device__ __forceinline__ void ldsm4(uint32_t* r, uint32_t addr) {
    asm volatile("ldmatrix.sync.aligned.m8n8.x4.shared.b16 {%0,%1,%2,%3}, [%4];"
                 : "=r"(r[0]), "=r"(r[1]), "=r"(r[2]), "=r"(r[3]) : "r"(addr));
}

// ---------------- shared GEMM core pieces ------------------------------------
#define BK 64
#define ATILE 16384                     // 128 rows x 128B
#define STAGE_BYTES (2 * ATILE)
#define GEMM_SMEM (2 * STAGE_BYTES)     // 64 KB

#define LOAD_STAGE(t) do {                                                    \
        uint32_t st_ = sbase + (uint32_t)((t) & 1) * STAGE_BYTES;             \
        int k0_ = (t) * BK;                                                   \
        _Pragma("unroll")                                                     \
        for (int i_ = 0; i_ < 8; i_++) {                                      \
            asm volatile("cp.async.cg.shared.global [%0], [%1], 16;"          \
                :: "r"(st_ + so0 + i_ * 2048u), "l"(gA0 + k0_ + i_ * gstep)); \
            asm volatile("cp.async.cg.shared.global [%0], [%1], 16;"          \
                :: "r"(st_ + ATILE + so0 + i_ * 2048u),                       \
                   "l"(gB0 + k0_ + i_ * gstep));                              \
        }                                                                     \
        asm volatile("cp.async.commit_group;" ::: "memory");                  \
    } while (0)

#define GEMM_BODY_MAIN()                                                      \
    const int g = lane >> 3, rin = lane & 7;                                  \
    const int ac = g >> 1;                                                    \
    uint32_t aoff[4], amask[4];                                               \
    _Pragma("unroll")                                                         \
    for (int mf = 0; mf < 4; mf++) {                                          \
        int ar = warp_m * 64 + mf * 16 + (g & 1) * 8 + rin;                   \
        aoff[mf] = (uint32_t)ar * 128;                                        \
        amask[mf] = (uint32_t)(ar & 7);                                       \
    }                                                                         \
    const int bc = g & 1;                                                     \
    uint32_t boff[4], bmask[4];                                               \
    _Pragma("unroll")                                                         \
    for (int p = 0; p < 4; p++) {                                             \
        int br = warp_n * 64 + (2 * p + (g >> 1)) * 8 + rin;                  \
        boff[p] = ATILE + (uint32_t)br * 128;                                 \
        bmask[p] = (uint32_t)(br & 7);                                        \
    }                                                                         \
    float acc[4][8][4];                                                       \
    _Pragma("unroll")                                                         \
    for (int mf = 0; mf < 4; mf++)                                            \
        _Pragma("unroll")                                                     \
        for (int nf = 0; nf < 8; nf++)                                        \
            _Pragma("unroll")                                                 \
            for (int j = 0; j < 4; j++) acc[mf][nf][j] = 0.f;                 \
    LOAD_STAGE(0);                                                            \
    LOAD_STAGE(1);                                                            \
    for (int s = 0; s < S; s++) {                                             \
        asm volatile("cp.async.wait_group %0;" :: "n"(1) : "memory");         \
        __syncthreads();                                                      \
        const uint32_t stg = sbase + (uint32_t)(s & 1) * STAGE_BYTES;         \
        _Pragma("unroll")                                                     \
        for (int kk = 0; kk < 4; kk++) {                                      \
            uint32_t bfr[4][4];                                               \
            _Pragma("unroll")                                                 \
            for (int p = 0; p < 4; p++)                                       \
                ldsm4(bfr[p], stg + boff[p] +                                 \
                      ((((uint32_t)(2 * kk + bc)) ^ bmask[p]) << 4));         \
            _Pragma("unroll")                                                 \
            for (int mf = 0; mf < 4; mf++) {                                  \
                uint32_t a[4];                                                \
                ldsm4(a, stg + aoff[mf] +                                     \
                      ((((uint32_t)(2 * kk + ac)) ^ amask[mf]) << 4));        \
                _Pragma("unroll")                                             \
                for (int nf = 0; nf < 8; nf++)                                \
                    mma_f16(acc[mf][nf], a, &bfr[nf >> 1][(nf & 1) * 2]);     \
            }                                                                 \
        }                                                                     \
        __syncthreads();                                                      \
        if (s + 2 < S) LOAD_STAGE(s + 2);                                     \
        else asm volatile("cp.async.commit_group;" ::: "memory");             \
    }

// ---------------- merged Q/K/V projection GEMM -------------------------------
// grid (10, 266): y<5 -> K-proj, 5<=y<10 -> V-proj (both K=2048, M=616),
// y>=10 -> Q-proj (K=1280, M=32768). KV tiles have the LOWEST linear block
// indices so they schedule in wave 0 and hide under Q's ~6 waves.
__global__ __launch_bounds__(128, 3)
void proj_gemm(const __half* __restrict__ hs_h, const __half* __restrict__ enc_h,
               const __half* __restrict__ wqt, const __half* __restrict__ wkt,
               const __half* __restrict__ wvt,
               __half* __restrict__ qo, __half* __restrict__ ko, __half* __restrict__ vo)
{
    extern __shared__ char smem[];
    const int yb = blockIdx.y;
    const __half* A; const __half* Bt; __half* C;
    int M, K, bm;
    if (yb < 10) {
        K = NCDIM; M = MKV; A = enc_h;
        if (yb < 5) { Bt = wkt; C = ko; bm = yb * 128; }
        else        { Bt = wvt; C = vo; bm = (yb - 5) * 128; }
    } else {
        K = ND; M = MQ; A = hs_h; Bt = wqt; C = qo; bm = (yb - 10) * 128;
    }
    const int S = K / BK;

    const int tid = threadIdx.x;
    const int wid = tid >> 5, lane = tid & 31;
    const int warp_m = wid & 1;
    const int warp_n = wid >> 1;
    const int bn = blockIdx.x * 128;
    const uint32_t sbase = (uint32_t)__cvta_generic_to_shared(smem);

    const int lrow = tid >> 3;
    const int lc16 = tid & 7;
    const __half* gA0 = A  + (size_t)(bm + lrow) * K + lc16 * 8;
    const __half* gB0 = Bt + (size_t)(bn + lrow) * K + lc16 * 8;
    const size_t gstep = (size_t)16 * K;
    const uint32_t so0 = (uint32_t)lrow * 128 + (uint32_t)((lc16 ^ (lrow & 7)) << 4);

    GEMM_BODY_MAIN()

#pragma unroll
    for (int mf = 0; mf < 4; mf++) {
        int r0 = bm + warp_m * 64 + mf * 16 + (lane >> 2);
#pragma unroll
        for (int half_ = 0; half_ < 2; half_++) {
            int r = r0 + half_ * 8;
            if (r >= M) continue;
            __half* crow = C + (size_t)r * ND + bn + warp_n * 64;
#pragma unroll
            for (int nf = 0; nf < 8; nf++) {
                int cc = nf * 8 + (lane & 3) * 2;
                *(__half2*)(crow + cc) =
                    __floats2half2_rn(acc[mf][nf][half_ * 2 + 0],
                                      acc[mf][nf][half_ * 2 + 1]);
            }
        }
    }
}

// ---------------- O-projection GEMM (f32 out, per-batch bias) ----------------
__global__ __launch_bounds__(128, 3)
void o_gemm(const __half* __restrict__ A, const __half* __restrict__ Bt,
            float* __restrict__ C, const float* __restrict__ bias)
{
    extern __shared__ char smem[];
    const int K = ND, S = K / BK;
    const int tid = threadIdx.x;
    const int wid = tid >> 5, lane = tid & 31;
    const int warp_m = wid & 1;
    const int warp_n = wid >> 1;
    const int bm = blockIdx.y * 128;
    const int bn = blockIdx.x * 128;
    const uint32_t sbase = (uint32_t)__cvta_generic_to_shared(smem);

    const int lrow = tid >> 3;
    const int lc16 = tid & 7;
    const __half* gA0 = A  + (size_t)(bm + lrow) * K + lc16 * 8;
    const __half* gB0 = Bt + (size_t)(bn + lrow) * K + lc16 * 8;
    const size_t gstep = (size_t)16 * K;
    const uint32_t so0 = (uint32_t)lrow * 128 + (uint32_t)((lc16 ^ (lrow & 7)) << 4);

    GEMM_BODY_MAIN()

#pragma unroll
    for (int mf = 0; mf < 4; mf++) {
        int r0 = bm + warp_m * 64 + mf * 16 + (lane >> 2);
#pragma unroll
        for (int half_ = 0; half_ < 2; half_++) {
            int r = r0 + half_ * 8;
            float* crow = C + (size_t)r * ND + bn + warp_n * 64;
            const float* brow = bias + (size_t)(r / NS) * ND + bn + warp_n * 64;
#pragma unroll
            for (int nf = 0; nf < 8; nf++) {
                int cc = nf * 8 + (lane & 3) * 2;
                *(float2*)(crow + cc) =
                    make_float2(acc[mf][nf][half_ * 2 + 0] + brow[cc],
                                acc[mf][nf][half_ * 2 + 1] + brow[cc + 1]);
            }
        }
    }
}

// ---------------- fp16 tensor-core attention (128 queries / CTA) ------------
#define VPITCH 88
#define A_QS 0
#define A_KS (128 * 64)
#define A_VT (A_KS + NKP * 64)
#define A_PS (A_VT + 64 * VPITCH)
#define ATTN_SMEM ((A_PS + 128 * VPITCH) * 2)

__global__ __launch_bounds__(256)
void attn_mma_kernel(const __half* __restrict__ q, const __half* __restrict__ kbuf,
                     const __half* __restrict__ vbuf, __half* __restrict__ out)
{
    extern __shared__ __half smh[];
    __half* Qs = smh + A_QS;
    __half* Ks = smh + A_KS;
    __half* Vt = smh + A_VT;
    __half* Ps = smh + A_PS;

    const int b = blockIdx.z;
    const int h = blockIdx.y;
    const int q0 = blockIdx.x * 128;
    const int tid = threadIdx.x;
    const int warp = tid >> 5, lane = tid & 31;
    const int rb = lane >> 2, cb = lane & 3;

    for (int i = tid; i < 128 * 8; i += 256) {
        int r = i >> 3, c = i & 7;
        uint4 t = *(const uint4*)&q[((size_t)(b * NS + q0 + r)) * ND + h * NHD + c * 8];
        *(uint4*)&Qs[r * 64 + ((c ^ (r & 7)) << 3)] = t;
    }
    for (int i = tid; i < NKP * 8; i += 256) {
        int r = i >> 3, c = i & 7;
        uint4 t = make_uint4(0u, 0u, 0u, 0u);
        if (r < NCTX)
            t = *(const uint4*)&kbuf[((size_t)(b * NCTX + r)) * ND + h * NHD + c * 8];
        *(uint4*)&Ks[r * 64 + ((c ^ (r & 7)) << 3)] = t;
    }
    for (int i = tid; i < NKP * NHD; i += 256) {
        int r = i >> 6, d = i & 63;
        __half t = (r < NCTX)
            ? vbuf[((size_t)(b * NCTX + r)) * ND + h * NHD + d] : __half(0.f);
        Vt[d * VPITCH + r] = t;
    }
    __syncthreads();

    const int qrow = warp * 16 + rb;

    float sacc[10][4];
#pragma unroll
    for (int nf = 0; nf < 10; nf++)
#pragma unroll
        for (int j = 0; j < 4; j++) sacc[nf][j] = 0.f;

#pragma unroll
    for (int kk = 0; kk < 4; kk++) {
        uint32_t a[4];
        {
            uint32_t a0 = (uint32_t)qrow * 128 + (((2 * kk) ^ rb) << 4) + cb * 4;
            const char* base = (const char*)Qs;
            a[0] = *(const uint32_t*)(base + a0);
            a[1] = *(const uint32_t*)(base + a0 + 1024);
            a[2] = *(const uint32_t*)(base + (a0 ^ 16));
            a[3] = *(const uint32_t*)(base + ((a0 + 1024) ^ 16));
        }
#pragma unroll
        for (int nf = 0; nf < 10; nf++) {
            int n = nf * 8 + rb;
            uint32_t b0 = (uint32_t)n * 128 + (((2 * kk) ^ rb) << 4) + cb * 4;
            const char* base = (const char*)Ks;
            uint32_t bf[2];
            bf[0] = *(const uint32_t*)(base + b0);
            bf[1] = *(const uint32_t*)(base + (b0 ^ 16));
            mma_f16(sacc[nf], a, bf);
        }
    }

    if (2 * cb >= 5)     { sacc[9][0] = -1e30f; sacc[9][2] = -1e30f; }
    if (2 * cb + 1 >= 5) { sacc[9][1] = -1e30f; sacc[9][3] = -1e30f; }

    float m0 = -1e30f, m1 = -1e30f;
#pragma unroll
    for (int nf = 0; nf < 10; nf++) {
        m0 = fmaxf(m0, fmaxf(sacc[nf][0], sacc[nf][1]));
        m1 = fmaxf(m1, fmaxf(sacc[nf][2], sacc[nf][3]));
    }
    m0 = fmaxf(m0, __shfl_xor_sync(0xFFFFFFFF, m0, 1));
    m0 = fmaxf(m0, __shfl_xor_sync(0xFFFFFFFF, m0, 2));
    m1 = fmaxf(m1, __shfl_xor_sync(0xFFFFFFFF, m1, 1));
    m1 = fmaxf(m1, __shfl_xor_sync(0xFFFFFFFF, m1, 2));

    float l0 = 0.f, l1 = 0.f;
#pragma unroll
    for (int nf = 0; nf < 10; nf++) {
        float p0 = __expf(sacc[nf][0] - m0);
        float p1 = __expf(sacc[nf][1] - m0);
        float p2 = __expf(sacc[nf][2] - m1);
        float p3 = __expf(sacc[nf][3] - m1);
        l0 += p0 + p1; l1 += p2 + p3;
        *(__half2*)&Ps[qrow * VPITCH + nf * 8 + 2 * cb]       = __floats2half2_rn(p0, p1);
        *(__half2*)&Ps[(qrow + 8) * VPITCH + nf * 8 + 2 * cb] = __floats2half2_rn(p2, p3);
    }
    l0 += __shfl_xor_sync(0xFFFFFFFF, l0, 1);
    l0 += __shfl_xor_sync(0xFFFFFFFF, l0, 2);
    l1 += __shfl_xor_sync(0xFFFFFFFF, l1, 1);
    l1 += __shfl_xor_sync(0xFFFFFFFF, l1, 2);
    __syncwarp();

    float oacc[8][4];
#pragma unroll
    for (int nf = 0; nf < 8; nf++)
#pragma unroll
        for (int j = 0; j < 4; j++) oacc[nf][j] = 0.f;

#pragma unroll
    for (int kk = 0; kk < 5; kk++) {
        uint32_t a[4];
        a[0] = *(const uint32_t*)&Ps[qrow * VPITCH + kk * 16 + 2 * cb];
        a[1] = *(const uint32_t*)&Ps[(qrow + 8) * VPITCH + kk * 16 + 2 * cb];
        a[2] = *(const uint32_t*)&Ps[qrow * VPITCH + kk * 16 + 8 + 2 * cb];
        a[3] = *(const uint32_t*)&Ps[(qrow + 8) * VPITCH + kk * 16 + 8 + 2 * cb];
#pragma unroll
        for (int nf = 0; nf < 8; nf++) {
            int n = nf * 8 + rb;
            uint32_t bf[2];
            bf[0] = *(const uint32_t*)&Vt[n * VPITCH + kk * 16 + 2 * cb];
            bf[1] = *(const uint32_t*)&Vt[n * VPITCH + kk * 16 + 8 + 2 * cb];
            mma_f16(oacc[nf], a, bf);
        }
    }

    const float inv0 = 1.f / l0, inv1 = 1.f / l1;
    __half* o0 = &out[((size_t)(b * NS + q0 + qrow)) * ND + h * NHD];
    __half* o1 = o0 + (size_t)8 * ND;
#pragma unroll
    for (int nf = 0; nf < 8; nf++) {
        int cc = nf * 8 + 2 * cb;
        *(__half2*)(o0 + cc) = __floats2half2_rn(oacc[nf][0] * inv0, oacc[nf][1] * inv0);
        *(__half2*)(o1 + cc) = __floats2half2_rn(oacc[nf][2] * inv1, oacc[nf][3] * inv1);
    }
}

// ---------------- preprocessing ---------------------------------------------
__global__ void f2h_copy(const float4* __restrict__ in, __half2* __restrict__ out, long n4)
{
    long i = (long)blockIdx.x * blockDim.x + threadIdx.x;
    if (i < n4) {
        float4 v = in[i];
        out[i * 2]     = __floats2half2_rn(v.x, v.y);
        out[i * 2 + 1] = __floats2half2_rn(v.z, v.w);
    }
}

__global__ void f2h_pad_enc(const float* __restrict__ enc, __half* __restrict__ out)
{
    long i = (long)blockIdx.x * blockDim.x + threadIdx.x;
    if (i < (long)MKV_PAD * NCDIM) {
        long row = i / NCDIM;
        out[i] = (row < MKV) ? __float2half_rn(enc[i]) : __half(0.f);
    }
}

// all four weight transposes in one launch (z selects the matrix)
__global__ void transpose_all_kernel(const float* __restrict__ Wq, const float* __restrict__ Wk,
                                     const float* __restrict__ Wv, const float* __restrict__ Wo,
                                     __half* __restrict__ wqt, __half* __restrict__ wkt,
                                     __half* __restrict__ wvt, __half* __restrict__ wot)
{
    const float* W; __half* Wt; int K; float scale = 1.f;
    switch (blockIdx.z) {
        case 0:  W = Wq; Wt = wqt; K = ND;    break;
        case 1:  W = Wk; Wt = wkt; K = NCDIM; scale = 0.125f; break;
        case 2:  W = Wv; Wt = wvt; K = NCDIM; break;
        default: W = Wo; Wt = wot; K = ND;    break;
    }
    int k0 = blockIdx.y * 32, n0 = blockIdx.x * 32;
    if (k0 >= K) return;
    __shared__ float t[32][33];
    int x = threadIdx.x, y = threadIdx.y;
#pragma unroll
    for (int i = 0; i < 32; i += 8)
        t[y + i][x] = W[(size_t)(k0 + y + i) * ND + n0 + x];
    __syncthreads();
#pragma unroll
    for (int i = 0; i < 32; i += 8)
        Wt[(size_t)(n0 + y + i) * K + k0 + x] = __float2half_rn(t[x][y + i] * scale);
}

// ---------------- adapter branch (batch-shared weight reads) ----------------
__global__ void adapter1_kernel(const float* __restrict__ ad,
                                const float* __restrict__ Wva,
                                float* __restrict__ tip)
{
    __shared__ float ad_s[NB * NADIM];
    __shared__ float red[16][8][NB];
    const int tid = threadIdx.x;
    const int jj = tid & 7, ks = tid >> 3;
    const int j = blockIdx.x * 8 + jj;
    for (int i = tid; i < NB * NADIM; i += 128) ad_s[i] = ad[i];
    __syncthreads();
    float s[NB];
#pragma unroll
    for (int b = 0; b < NB; b++) s[b] = 0.f;
#pragma unroll 4
    for (int a = ks; a < NADIM; a += 16) {
        float w = Wva[(size_t)a * ND + j];
#pragma unroll
        for (int b = 0; b < NB; b++) s[b] += ad_s[b * NADIM + a] * w;
    }
#pragma unroll
    for (int b = 0; b < NB; b++) red[ks][jj][b] = s[b];
    __syncthreads();
    if (tid < 64) {
        int j2 = tid & 7, b = tid >> 3;
        float t = 0.f;
#pragma unroll
        for (int k = 0; k < 16; k++) t += red[k][j2][b];
        tip[b * ND + blockIdx.x * 8 + j2] = t;
    }
}

__global__ void adapter2_kernel(const float* __restrict__ tip,
                                const float* __restrict__ Wo,
                                const float* __restrict__ bo,
                                float* __restrict__ bias)
{
    __shared__ float tip_s[NB * ND];
    __shared__ float red[16][8][NB];
    const int tid = threadIdx.x;
    const int jj = tid & 7, ks = tid >> 3;
    const int j = blockIdx.x * 8 + jj;
    for (int i = tid; i < NB * ND; i += 128) tip_s[i] = tip[i];
    __syncthreads();
    float s[NB];
#pragma unroll
    for (int b = 0; b < NB; b++) s[b] = 0.f;
#pragma unroll 4
    for (int kk = ks; kk < ND; kk += 16) {
        float w = Wo[(size_t)kk * ND + j];
#pragma unroll
        for (int b = 0; b < NB; b++) s[b] += tip_s[b * ND + kk] * w;
    }
#pragma unroll
    for (int b = 0; b < NB; b++) red[ks][jj][b] = s[b];
    __syncthreads();
    if (tid < 64) {
        int j2 = tid & 7, b = tid >> 3;
        float t = 0.f;
#pragma unroll
        for (int k = 0; k < 16; k++) t += red[k][j2][b];
        int col = blockIdx.x * 8 + j2;
        bias[b * ND + col] = bo[col] + t;
    }
}

// ---------------------------------------------------------------------------
extern "C" void kernel_launch(void* const* d_in, const int* in_sizes, int n_in,
                              void* d_out, int out_size)
{
    const float* hs  = (const float*)d_in[0];
    const float* enc = (const float*)d_in[1];
    const float* ad  = (const float*)d_in[2];
    const float* Wq  = (const float*)d_in[3];
    const float* Wk  = (const float*)d_in[4];
    const float* Wv  = (const float*)d_in[5];
    // d_in[6] = Wk_adapter: unused (softmax over a single key is identically 1)
    const float* Wva = (const float*)d_in[7];
    const float* Wo  = (const float*)d_in[8];
    const float* bo  = (const float*)d_in[9];
    float* out = (float*)d_out;

    __half *hs_h, *q, *attn_o, *enc_h, *kbuf, *vbuf, *wqt, *wot, *wkt, *wvt;
    float *tip, *bias;
    cudaGetSymbolAddress((void**)&hs_h,   g_hs_h);
    cudaGetSymbolAddress((void**)&q,      g_q);
    cudaGetSymbolAddress((void**)&attn_o, g_attn);
    cudaGetSymbolAddress((void**)&enc_h,  g_enc_h);
    cudaGetSymbolAddress((void**)&kbuf,   g_k);
    cudaGetSymbolAddress((void**)&vbuf,   g_v);
    cudaGetSymbolAddress((void**)&wqt,    g_wqt);
    cudaGetSymbolAddress((void**)&wot,    g_wot);
    cudaGetSymbolAddress((void**)&wkt,    g_wkt);
    cudaGetSymbolAddress((void**)&wvt,    g_wvt);
    cudaGetSymbolAddress((void**)&tip,    g_tip);
    cudaGetSymbolAddress((void**)&bias,   g_bias);

    cudaFuncSetAttribute(proj_gemm, cudaFuncAttributeMaxDynamicSharedMemorySize, GEMM_SMEM);
    cudaFuncSetAttribute(o_gemm,    cudaFuncAttributeMaxDynamicSharedMemorySize, GEMM_SMEM);
    cudaFuncSetAttribute(attn_mma_kernel, cudaFuncAttributeMaxDynamicSharedMemorySize, ATTN_SMEM);

    long n4 = (long)MQ * ND / 4;
    // ncu captures launch index 3 -> merged QKV projection placed there
    f2h_copy<<<(unsigned)((n4 + 255) / 256), 256>>>((const float4*)hs, (__half2*)hs_h, n4);   // 0
    f2h_pad_enc<<<(unsigned)(((long)MKV_PAD * NCDIM + 255) / 256), 256>>>(enc, enc_h);        // 1
    transpose_all_kernel<<<dim3(ND / 32, NCDIM / 32, 4), dim3(32, 8)>>>(                      // 2
        Wq, Wk, Wv, Wo, wqt, wkt, wvt, wot);

    // merged Q/K/V projections — KV tiles get the lowest block indices
    proj_gemm<<<dim3(ND / 128, 10 + MQ / 128, 1), 128, GEMM_SMEM>>>(                          // 3 (profiled)
        hs_h, enc_h, wqt, wkt, wvt, q, kbuf, vbuf);

    adapter1_kernel<<<ND / 8, 128>>>(ad, Wva, tip);
    adapter2_kernel<<<ND / 8, 128>>>(tip, Wo, bo, bias);

    // fp16 tensor-core attention (128 queries/CTA) -> fp16 output
    attn_mma_kernel<<<dim3(NS / 128, NHEADS, NB), 256, ATTN_SMEM>>>(q, kbuf, vbuf, attn_o);

    // output projection + per-batch adapter bias (bo folded into bias), f32 out
    o_gemm<<<dim3(ND / 128, MQ / 128, 1), 128, GEMM_SMEM>>>(attn_o, wot, out, bias);
}

// round 13
// speedup vs baseline: 1.0749x; 1.0749x over previous
#include <cuda_runtime.h>
#include <cuda_fp16.h>
#include <cstdint>
#include <math.h>

#define NB     8
#define NS     4096
#define ND     1280
#define NCTX   77
#define NKP    80          // padded keys
#define NCDIM  2048
#define NADIM  768
#define NHEADS 20
#define NHD    64
#define MQ     (NB*NS)     // 32768
#define MKV    616
#define MKV_PAD 640
#define KVSPLIT 3

// ---------------- scratch (device globals; no allocation allowed) -----------
__device__ __half g_hs_h[MQ * ND];           // fp16(hidden_states)
__device__ __half g_q[MQ * ND];              // Q projection (fp16)
__device__ __half g_attn[MQ * ND];           // attention out (fp16)
__device__ __half g_enc_h[MKV_PAD * NCDIM];  // fp16(encoder), padded rows
__device__ __half g_k[MKV * ND];             // K fp16 (0.125 folded into wkt)
__device__ __half g_v[MKV * ND];
__device__ __half g_wqt[ND * ND];            // W^T fp16  [N,K]
__device__ __half g_wot[ND * ND];
__device__ __half g_wkt[ND * NCDIM];         // includes 0.125 scale
__device__ __half g_wvt[ND * NCDIM];
__device__ float  g_kvpart[2 * KVSPLIT * MKV_PAD * ND];  // split-K partials
__device__ float  g_tip[NB * ND];
__device__ float  g_bias[NB * ND];

__device__ __forceinline__ void mma_f16(float* d, const uint32_t* a, const uint32_t* b) {
    asm volatile("mma.sync.aligned.m16n8k16.row.col.f32.f16.f16.f32 "
                 "{%0,%1,%2,%3}, {%4,%5,%6,%7}, {%8,%9}, {%0,%1,%2,%3};"
                 : "+f"(d[0]), "+f"(d[1]), "+f"(d[2]), "+f"(d[3])
                 : "r"(a[0]), "r"(a[1]), "r"(a[2]), "r"(a[3]),
                   "r"(b[0]), "r"(b[1]));
}
__device__ __forceinline__ void ldsm4(uint32_t* r, uint32_t addr) {
    asm volatile("ldmatrix.sync.aligned.m8n8.x4.shared.b16 {%0,%1,%2,%3}, [%4];"
                 : "=r"(r[0]), "=r"(r[1]), "=r"(r[2]), "=r"(r[3]) : "r"(addr));
}
__device__ __forceinline__ uint32_t pack_h2(float lo, float hi) {
    __half2 t = __floats2half2_rn(lo, hi);
    return *reinterpret_cast<uint32_t*>(&t);
}

// ---------------- shared GEMM core pieces ------------------------------------
#define BK 64
#define ATILE 16384                     // 128 rows x 128B
#define STAGE_BYTES (2 * ATILE)
#define GEMM_SMEM (2 * STAGE_BYTES)     // 64 KB

#define LOAD_STAGE(t) do {                                                    \
        uint32_t st_ = sbase + (uint32_t)((t) & 1) * STAGE_BYTES;             \
        int k0_ = (t) * BK;                                                   \
        _Pragma("unroll")                                                     \
        for (int i_ = 0; i_ < 8; i_++) {                                      \
            asm volatile("cp.async.cg.shared.global [%0], [%1], 16;"          \
                :: "r"(st_ + so0 + i_ * 2048u), "l"(gA0 + k0_ + i_ * gstep)); \
            asm volatile("cp.async.cg.shared.global [%0], [%1], 16;"          \
                :: "r"(st_ + ATILE + so0 + i_ * 2048u),                       \
                   "l"(gB0 + k0_ + i_ * gstep));                              \
        }                                                                     \
        asm volatile("cp.async.commit_group;" ::: "memory");                  \
    } while (0)

#define GEMM_BODY_MAIN()                                                      \
    const int g = lane >> 3, rin = lane & 7;                                  \
    const int ac = g >> 1;                                                    \
    uint32_t aoff[4], amask[4];                                               \
    _Pragma("unroll")                                                         \
    for (int mf = 0; mf < 4; mf++) {                                          \
        int ar = warp_m * 64 + mf * 16 + (g & 1) * 8 + rin;                   \
        aoff[mf] = (uint32_t)ar * 128;                                        \
        amask[mf] = (uint32_t)(ar & 7);                                       \
    }                                                                         \
    const int bc = g & 1;                                                     \
    uint32_t boff[4], bmask[4];                                               \
    _Pragma("unroll")                                                         \
    for (int p = 0; p < 4; p++) {                                             \
        int br = warp_n * 64 + (2 * p + (g >> 1)) * 8 + rin;                  \
        boff[p] = ATILE + (uint32_t)br * 128;                                 \
        bmask[p] = (uint32_t)(br & 7);                                        \
    }                                                                         \
    float acc[4][8][4];                                                       \
    _Pragma("unroll")                                                         \
    for (int mf = 0; mf < 4; mf++)                                            \
        _Pragma("unroll")                                                     \
        for (int nf = 0; nf < 8; nf++)                                        \
            _Pragma("unroll")                                                 \
            for (int j = 0; j < 4; j++) acc[mf][nf][j] = 0.f;                 \
    LOAD_STAGE(0);                                                            \
    LOAD_STAGE(1);                                                            \
    for (int s = 0; s < S; s++) {                                             \
        asm volatile("cp.async.wait_group %0;" :: "n"(1) : "memory");         \
        __syncthreads();                                                      \
        const uint32_t stg = sbase + (uint32_t)(s & 1) * STAGE_BYTES;         \
        _Pragma("unroll")                                                     \
        for (int kk = 0; kk < 4; kk++) {                                      \
            uint32_t bfr[4][4];                                               \
            _Pragma("unroll")                                                 \
            for (int p = 0; p < 4; p++)                                       \
                ldsm4(bfr[p], stg + boff[p] +                                 \
                      ((((uint32_t)(2 * kk + bc)) ^ bmask[p]) << 4));         \
            _Pragma("unroll")                                                 \
            for (int mf = 0; mf < 4; mf++) {                                  \
                uint32_t a[4];                                                \
                ldsm4(a, stg + aoff[mf] +                                     \
                      ((((uint32_t)(2 * kk + ac)) ^ amask[mf]) << 4));        \
                _Pragma("unroll")                                             \
                for (int nf = 0; nf < 8; nf++)                                \
                    mma_f16(acc[mf][nf], a, &bfr[nf >> 1][(nf & 1) * 2]);     \
            }                                                                 \
        }                                                                     \
        __syncthreads();                                                      \
        if (s + 2 < S) LOAD_STAGE(s + 2);                                     \
        else asm volatile("cp.async.commit_group;" ::: "memory");             \
    }

// ---------------- main fp16 GEMM (Q-proj / O-proj) ---------------------------
template <typename OutT>
__global__ __launch_bounds__(128, 3)
void h16_gemm(const __half* __restrict__ A, const __half* __restrict__ Bt,
              OutT* __restrict__ C, int M, int K, int Ntot,
              const float* __restrict__ bias, int rows_per_batch)
{
    extern __shared__ char smem[];
    const int tid = threadIdx.x;
    const int wid = tid >> 5, lane = tid & 31;
    const int warp_m = wid & 1;
    const int warp_n = wid >> 1;
    const int bm = blockIdx.y * 128;
    const int bn = blockIdx.x * 128;
    const int S = K / BK;
    const uint32_t sbase = (uint32_t)__cvta_generic_to_shared(smem);

    const int lrow = tid >> 3;
    const int lc16 = tid & 7;
    const __half* gA0 = A  + (size_t)(bm + lrow) * K + lc16 * 8;
    const __half* gB0 = Bt + (size_t)(bn + lrow) * K + lc16 * 8;
    const size_t gstep = (size_t)16 * K;
    const uint32_t so0 = (uint32_t)lrow * 128 + (uint32_t)((lc16 ^ (lrow & 7)) << 4);

    GEMM_BODY_MAIN()

#pragma unroll
    for (int mf = 0; mf < 4; mf++) {
        int r0 = bm + warp_m * 64 + mf * 16 + (lane >> 2);
#pragma unroll
        for (int half_ = 0; half_ < 2; half_++) {
            int r = r0 + half_ * 8;
            if (r >= M) continue;
            OutT* crow = C + (size_t)r * Ntot + bn + warp_n * 64;
            const float* brow = bias
                ? bias + (size_t)(r / rows_per_batch) * Ntot + bn + warp_n * 64
                : nullptr;
#pragma unroll
            for (int nf = 0; nf < 8; nf++) {
                int cc = nf * 8 + (lane & 3) * 2;
                float ox = acc[mf][nf][half_ * 2 + 0];
                float oy = acc[mf][nf][half_ * 2 + 1];
                if (bias) { ox += brow[cc]; oy += brow[cc + 1]; }
                if constexpr (sizeof(OutT) == 2) {
                    *(__half2*)(crow + cc) = __floats2half2_rn(ox, oy);
                } else {
                    *(float2*)(crow + cc) = make_float2(ox, oy);
                }
            }
        }
    }
}

// ---------------- split-K KV projection --------------------------------------
// grid (10, 5, 2*KVSPLIT): z = split*2 + kv. f32 partials to g_kvpart.
__global__ __launch_bounds__(128, 3)
void kv_gemm(const __half* __restrict__ enc_h, const __half* __restrict__ wkt,
             const __half* __restrict__ wvt, float* __restrict__ part)
{
    extern __shared__ char smem[];
    const int kv = blockIdx.z & 1;
    const int sp = blockIdx.z >> 1;                  // 0..KVSPLIT-1
    const int s_begin = (sp == 0) ? 0 : (sp == 1 ? 11 : 22);
    const int S = (sp == 2) ? 10 : 11;
    const __half* Bt = kv ? wvt : wkt;

    const int tid = threadIdx.x;
    const int wid = tid >> 5, lane = tid & 31;
    const int warp_m = wid & 1;
    const int warp_n = wid >> 1;
    const int bm = blockIdx.y * 128;
    const int bn = blockIdx.x * 128;
    const uint32_t sbase = (uint32_t)__cvta_generic_to_shared(smem);

    const int lrow = tid >> 3;
    const int lc16 = tid & 7;
    const __half* gA0 = enc_h + (size_t)(bm + lrow) * NCDIM + s_begin * BK + lc16 * 8;
    const __half* gB0 = Bt    + (size_t)(bn + lrow) * NCDIM + s_begin * BK + lc16 * 8;
    const size_t gstep = (size_t)16 * NCDIM;
    const uint32_t so0 = (uint32_t)lrow * 128 + (uint32_t)((lc16 ^ (lrow & 7)) << 4);

    GEMM_BODY_MAIN()

    float* base = part + ((size_t)(kv * KVSPLIT + sp)) * MKV_PAD * ND;
#pragma unroll
    for (int mf = 0; mf < 4; mf++) {
        int r0 = bm + warp_m * 64 + mf * 16 + (lane >> 2);
#pragma unroll
        for (int half_ = 0; half_ < 2; half_++) {
            int r = r0 + half_ * 8;
            float* crow = base + (size_t)r * ND + bn + warp_n * 64;
#pragma unroll
            for (int nf = 0; nf < 8; nf++) {
                int cc = nf * 8 + (lane & 3) * 2;
                *(float2*)(crow + cc) =
                    make_float2(acc[mf][nf][half_ * 2 + 0],
                                acc[mf][nf][half_ * 2 + 1]);
            }
        }
    }
}

// sum the split partials -> fp16 K/V buffers (rows < MKV only)
__global__ void kv_reduce(const float* __restrict__ part,
                          __half* __restrict__ kbuf, __half* __restrict__ vbuf)
{
    long i = (long)blockIdx.x * blockDim.x + threadIdx.x;   // float4 groups
    const long n4 = (long)2 * MKV * ND / 4;
    if (i >= n4) return;
    long e = i * 4;
    int kv = (int)(e / ((long)MKV * ND));
    long rem = e - (long)kv * MKV * ND;
    const float* b = part + (size_t)kv * KVSPLIT * MKV_PAD * ND + rem;
    float4 p0 = *(const float4*)(b);
    float4 p1 = *(const float4*)(b + (size_t)MKV_PAD * ND);
    float4 p2 = *(const float4*)(b + (size_t)2 * MKV_PAD * ND);
    __half* o = (kv ? vbuf : kbuf) + rem;
    *(__half2*)(o)     = __floats2half2_rn(p0.x + p1.x + p2.x, p0.y + p1.y + p2.y);
    *(__half2*)(o + 2) = __floats2half2_rn(p0.z + p1.z + p2.z, p0.w + p1.w + p2.w);
}

// ---------------- fp16 tensor-core attention (register-resident P) ----------
// 256 threads = 8 warps, 128 queries/CTA.
// smem halfs: Qs 128x64 swz | Ks 80x64 swz | Vt 64x88
#define VPITCH 88
#define A_QS 0
#define A_KS (128 * 64)
#define A_VT (A_KS + NKP * 64)
#define ATTN_SMEM ((A_VT + 64 * VPITCH) * 2)   // 37888 B

__global__ __launch_bounds__(256)
void attn_mma_kernel(const __half* __restrict__ q, const __half* __restrict__ kbuf,
                     const __half* __restrict__ vbuf, __half* __restrict__ out)
{
    extern __shared__ __half smh[];
    __half* Qs = smh + A_QS;
    __half* Ks = smh + A_KS;
    __half* Vt = smh + A_VT;

    const int b = blockIdx.z;
    const int h = blockIdx.y;
    const int q0 = blockIdx.x * 128;
    const int tid = threadIdx.x;
    const int warp = tid >> 5, lane = tid & 31;
    const int rb = lane >> 2, cb = lane & 3;

    for (int i = tid; i < 128 * 8; i += 256) {
        int r = i >> 3, c = i & 7;
        uint4 t = *(const uint4*)&q[((size_t)(b * NS + q0 + r)) * ND + h * NHD + c * 8];
        *(uint4*)&Qs[r * 64 + ((c ^ (r & 7)) << 3)] = t;
    }
    for (int i = tid; i < NKP * 8; i += 256) {
        int r = i >> 3, c = i & 7;
        uint4 t = make_uint4(0u, 0u, 0u, 0u);
        if (r < NCTX)
            t = *(const uint4*)&kbuf[((size_t)(b * NCTX + r)) * ND + h * NHD + c * 8];
        *(uint4*)&Ks[r * 64 + ((c ^ (r & 7)) << 3)] = t;
    }
    for (int i = tid; i < NKP * NHD; i += 256) {
        int r = i >> 6, d = i & 63;
        __half t = (r < NCTX)
            ? vbuf[((size_t)(b * NCTX + r)) * ND + h * NHD + d] : __half(0.f);
        Vt[d * VPITCH + r] = t;
    }
    __syncthreads();

    const int qrow = warp * 16 + rb;

    // ---- S = Q K^T ----
    float sacc[10][4];
#pragma unroll
    for (int nf = 0; nf < 10; nf++)
#pragma unroll
        for (int j = 0; j < 4; j++) sacc[nf][j] = 0.f;

#pragma unroll
    for (int kk = 0; kk < 4; kk++) {
        uint32_t a[4];
        {
            uint32_t a0 = (uint32_t)qrow * 128 + (((2 * kk) ^ rb) << 4) + cb * 4;
            const char* base = (const char*)Qs;
            a[0] = *(const uint32_t*)(base + a0);
            a[1] = *(const uint32_t*)(base + a0 + 1024);
            a[2] = *(const uint32_t*)(base + (a0 ^ 16));
            a[3] = *(const uint32_t*)(base + ((a0 + 1024) ^ 16));
        }
#pragma unroll
        for (int nf = 0; nf < 10; nf++) {
            int n = nf * 8 + rb;
            uint32_t b0 = (uint32_t)n * 128 + (((2 * kk) ^ rb) << 4) + cb * 4;
            const char* base = (const char*)Ks;
            uint32_t bf[2];
            bf[0] = *(const uint32_t*)(base + b0);
            bf[1] = *(const uint32_t*)(base + (b0 ^ 16));
            mma_f16(sacc[nf], a, bf);
        }
    }

    // mask padded keys (cols 77..79 in nf=9)
    if (2 * cb >= 5)     { sacc[9][0] = -1e30f; sacc[9][2] = -1e30f; }
    if (2 * cb + 1 >= 5) { sacc[9][1] = -1e30f; sacc[9][3] = -1e30f; }

    // ---- softmax: P stays in registers, packed directly as A fragments ----
    float m0 = -1e30f, m1 = -1e30f;
#pragma unroll
    for (int nf = 0; nf < 10; nf++) {
        m0 = fmaxf(m0, fmaxf(sacc[nf][0], sacc[nf][1]));
        m1 = fmaxf(m1, fmaxf(sacc[nf][2], sacc[nf][3]));
    }
    m0 = fmaxf(m0, __shfl_xor_sync(0xFFFFFFFF, m0, 1));
    m0 = fmaxf(m0, __shfl_xor_sync(0xFFFFFFFF, m0, 2));
    m1 = fmaxf(m1, __shfl_xor_sync(0xFFFFFFFF, m1, 1));
    m1 = fmaxf(m1, __shfl_xor_sync(0xFFFFFFFF, m1, 2));

    float l0 = 0.f, l1 = 0.f;
    uint32_t pfrag[10][2];
#pragma unroll
    for (int nf = 0; nf < 10; nf++) {
        float p0 = __expf(sacc[nf][0] - m0);
        float p1 = __expf(sacc[nf][1] - m0);
        float p2 = __expf(sacc[nf][2] - m1);
        float p3 = __expf(sacc[nf][3] - m1);
        l0 += p0 + p1; l1 += p2 + p3;
        pfrag[nf][0] = pack_h2(p0, p1);   // rows r
        pfrag[nf][1] = pack_h2(p2, p3);   // rows r+8
    }
    l0 += __shfl_xor_sync(0xFFFFFFFF, l0, 1);
    l0 += __shfl_xor_sync(0xFFFFFFFF, l0, 2);
    l1 += __shfl_xor_sync(0xFFFFFFFF, l1, 1);
    l1 += __shfl_xor_sync(0xFFFFFFFF, l1, 2);

    // ---- O = P · Vt^T  (5 x k16 = 80 keys); P fragments already in regs ----
    float oacc[8][4];
#pragma unroll
    for (int nf = 0; nf < 8; nf++)
#pragma unroll
        for (int j = 0; j < 4; j++) oacc[nf][j] = 0.f;

#pragma unroll
    for (int kk = 0; kk < 5; kk++) {
        uint32_t a[4];
        a[0] = pfrag[2 * kk][0];       // (r,   k_lo)
        a[1] = pfrag[2 * kk][1];       // (r+8, k_lo)
        a[2] = pfrag[2 * kk + 1][0];   // (r,   k_hi)
        a[3] = pfrag[2 * kk + 1][1];   // (r+8, k_hi)
#pragma unroll
        for (int nf = 0; nf < 8; nf++) {
            int n = nf * 8 + rb;
            uint32_t bf[2];
            bf[0] = *(const uint32_t*)&Vt[n * VPITCH + kk * 16 + 2 * cb];
            bf[1] = *(const uint32_t*)&Vt[n * VPITCH + kk * 16 + 8 + 2 * cb];
            mma_f16(oacc[nf], a, bf);
        }
    }

    const float inv0 = 1.f / l0, inv1 = 1.f / l1;
    __half* o0 = &out[((size_t)(b * NS + q0 + qrow)) * ND + h * NHD];
    __half* o1 = o0 + (size_t)8 * ND;
#pragma unroll
    for (int nf = 0; nf < 8; nf++) {
        int cc = nf * 8 + 2 * cb;
        *(__half2*)(o0 + cc) = __floats2half2_rn(oacc[nf][0] * inv0, oacc[nf][1] * inv0);
        *(__half2*)(o1 + cc) = __floats2half2_rn(oacc[nf][2] * inv1, oacc[nf][3] * inv1);
    }
}

// ---------------- preprocessing ---------------------------------------------
__global__ void f2h_copy(const float4* __restrict__ in, __half2* __restrict__ out, long n4)
{
    long i = (long)blockIdx.x * blockDim.x + threadIdx.x;
    if (i < n4) {
        float4 v = in[i];
        out[i * 2]     = __floats2half2_rn(v.x, v.y);
        out[i * 2 + 1] = __floats2half2_rn(v.z, v.w);
    }
}

__global__ void f2h_pad_enc(const float* __restrict__ enc, __half* __restrict__ out)
{
    long i = (long)blockIdx.x * blockDim.x + threadIdx.x;
    if (i < (long)MKV_PAD * NCDIM) {
        long row = i / NCDIM;
        out[i] = (row < MKV) ? __float2half_rn(enc[i]) : __half(0.f);
    }
}

// all four weight transposes in one launch (z selects the matrix)
__global__ void transpose_all_kernel(const float* __restrict__ Wq, const float* __restrict__ Wk,
                                     const float* __restrict__ Wv, const float* __restrict__ Wo,
                                     __half* __restrict__ wqt, __half* __restrict__ wkt,
                                     __half* __restrict__ wvt, __half* __restrict__ wot)
{
    const float* W; __half* Wt; int K; float scale = 1.f;
    switch (blockIdx.z) {
        case 0:  W = Wq; Wt = wqt; K = ND;    break;
        case 1:  W = Wk; Wt = wkt; K = NCDIM; scale = 0.125f; break;
        case 2:  W = Wv; Wt = wvt; K = NCDIM; break;
        default: W = Wo; Wt = wot; K = ND;    break;
    }
    int k0 = blockIdx.y * 32, n0 = blockIdx.x * 32;
    if (k0 >= K) return;
    __shared__ float t[32][33];
    int x = threadIdx.x, y = threadIdx.y;
#pragma unroll
    for (int i = 0; i < 32; i += 8)
        t[y + i][x] = W[(size_t)(k0 + y + i) * ND + n0 + x];
    __syncthreads();
#pragma unroll
    for (int i = 0; i < 32; i += 8)
        Wt[(size_t)(n0 + y + i) * K + k0 + x] = __float2half_rn(t[x][y + i] * scale);
}

// ---------------- adapter branch (batch-shared weight reads) ----------------
__global__ void adapter1_kernel(const float* __restrict__ ad,
                                const float* __restrict__ Wva,
                                float* __restrict__ tip)
{
    __shared__ float ad_s[NB * NADIM];
    __shared__ float red[16][8][NB];
    const int tid = threadIdx.x;
    const int jj = tid & 7, ks = tid >> 3;
    const int j = blockIdx.x * 8 + jj;
    for (int i = tid; i < NB * NADIM; i += 128) ad_s[i] = ad[i];
    __syncthreads();
    float s[NB];
#pragma unroll
    for (int b = 0; b < NB; b++) s[b] = 0.f;
#pragma unroll 4
    for (int a = ks; a < NADIM; a += 16) {
        float w = Wva[(size_t)a * ND + j];
#pragma unroll
        for (int b = 0; b < NB; b++) s[b] += ad_s[b * NADIM + a] * w;
    }
#pragma unroll
    for (int b = 0; b < NB; b++) red[ks][jj][b] = s[b];
    __syncthreads();
    if (tid < 64) {
        int j2 = tid & 7, b = tid >> 3;
        float t = 0.f;
#pragma unroll
        for (int k = 0; k < 16; k++) t += red[k][j2][b];
        tip[b * ND + blockIdx.x * 8 + j2] = t;
    }
}

__global__ void adapter2_kernel(const float* __restrict__ tip,
                                const float* __restrict__ Wo,
                                const float* __restrict__ bo,
                                float* __restrict__ bias)
{
    __shared__ float tip_s[NB * ND];
    __shared__ float red[16][8][NB];
    const int tid = threadIdx.x;
    const int jj = tid & 7, ks = tid >> 3;
    const int j = blockIdx.x * 8 + jj;
    for (int i = tid; i < NB * ND; i += 128) tip_s[i] = tip[i];
    __syncthreads();
    float s[NB];
#pragma unroll
    for (int b = 0; b < NB; b++) s[b] = 0.f;
#pragma unroll 4
    for (int kk = ks; kk < ND; kk += 16) {
        float w = Wo[(size_t)kk * ND + j];
#pragma unroll
        for (int b = 0; b < NB; b++) s[b] += tip_s[b * ND + kk] * w;
    }
#pragma unroll
    for (int b = 0; b < NB; b++) red[ks][jj][b] = s[b];
    __syncthreads();
    if (tid < 64) {
        int j2 = tid & 7, b = tid >> 3;
        float t = 0.f;
#pragma unroll
        for (int k = 0; k < 16; k++) t += red[k][j2][b];
        int col = blockIdx.x * 8 + j2;
        bias[b * ND + col] = bo[col] + t;
    }
}

// ---------------------------------------------------------------------------
extern "C" void kernel_launch(void* const* d_in, const int* in_sizes, int n_in,
                              void* d_out, int out_size)
{
    const float* hs  = (const float*)d_in[0];
    const float* enc = (const float*)d_in[1];
    const float* ad  = (const float*)d_in[2];
    const float* Wq  = (const float*)d_in[3];
    const float* Wk  = (const float*)d_in[4];
    const float* Wv  = (const float*)d_in[5];
    // d_in[6] = Wk_adapter: unused (softmax over a single key is identically 1)
    const float* Wva = (const float*)d_in[7];
    const float* Wo  = (const float*)d_in[8];
    const float* bo  = (const float*)d_in[9];
    float* out = (float*)d_out;

    __half *hs_h, *q, *attn_o, *enc_h, *kbuf, *vbuf, *wqt, *wot, *wkt, *wvt;
    float *tip, *bias, *kvpart;
    cudaGetSymbolAddress((void**)&hs_h,   g_hs_h);
    cudaGetSymbolAddress((void**)&q,      g_q);
    cudaGetSymbolAddress((void**)&attn_o, g_attn);
    cudaGetSymbolAddress((void**)&enc_h,  g_enc_h);
    cudaGetSymbolAddress((void**)&kbuf,   g_k);
    cudaGetSymbolAddress((void**)&vbuf,   g_v);
    cudaGetSymbolAddress((void**)&wqt,    g_wqt);
    cudaGetSymbolAddress((void**)&wot,    g_wot);
    cudaGetSymbolAddress((void**)&wkt,    g_wkt);
    cudaGetSymbolAddress((void**)&wvt,    g_wvt);
    cudaGetSymbolAddress((void**)&kvpart, g_kvpart);
    cudaGetSymbolAddress((void**)&tip,    g_tip);
    cudaGetSymbolAddress((void**)&bias,   g_bias);

    cudaFuncSetAttribute(h16_gemm<float>,  cudaFuncAttributeMaxDynamicSharedMemorySize, GEMM_SMEM);
    cudaFuncSetAttribute(h16_gemm<__half>, cudaFuncAttributeMaxDynamicSharedMemorySize, GEMM_SMEM);
    cudaFuncSetAttribute(kv_gemm,          cudaFuncAttributeMaxDynamicSharedMemorySize, GEMM_SMEM);
    cudaFuncSetAttribute(attn_mma_kernel,  cudaFuncAttributeMaxDynamicSharedMemorySize, ATTN_SMEM);

    long n4 = (long)MQ * ND / 4;
    // ncu captures launch index 3 -> Q-projection GEMM placed there
    f2h_copy<<<(unsigned)((n4 + 255) / 256), 256>>>((const float4*)hs, (__half2*)hs_h, n4);   // 0
    f2h_pad_enc<<<(unsigned)(((long)MKV_PAD * NCDIM + 255) / 256), 256>>>(enc, enc_h);        // 1
    transpose_all_kernel<<<dim3(ND / 32, NCDIM / 32, 4), dim3(32, 8)>>>(                      // 2
        Wq, Wk, Wv, Wo, wqt, wkt, wvt, wot);
    h16_gemm<__half><<<dim3(ND / 128, MQ / 128), 128, GEMM_SMEM>>>(                           // 3 (profiled)
        hs_h, wqt, q, MQ, ND, ND, nullptr, 1);

    // split-K KV projections (0.125 folded into wkt)
    kv_gemm<<<dim3(ND / 128, MKV_PAD / 128, 2 * KVSPLIT), 128, GEMM_SMEM>>>(
        enc_h, wkt, wvt, kvpart);
    {
        long r4 = (long)2 * MKV * ND / 4;
        kv_reduce<<<(unsigned)((r4 + 255) / 256), 256>>>(kvpart, kbuf, vbuf);
    }

    adapter1_kernel<<<ND / 8, 128>>>(ad, Wva, tip);
    adapter2_kernel<<<ND / 8, 128>>>(tip, Wo, bo, bias);

    // fp16 tensor-core attention (128 queries/CTA, register-resident P)
    attn_mma_kernel<<<dim3(NS / 128, NHEADS, NB), 256, ATTN_SMEM>>>(q, kbuf, vbuf, attn_o);

    // output projection + per-batch adapter bias (bo folded into bias), f32 out
    h16_gemm<float><<<dim3(ND / 128, MQ / 128), 128, GEMM_SMEM>>>(
        attn_o, wot, out, MQ, ND, ND, bias, NS);
}

// round 14
// speedup vs baseline: 1.1682x; 1.0868x over previous
#include <cuda_runtime.h>
#include <cuda_fp16.h>
#include <cstdint>
#include <math.h>

#define NB     8
#define NS     4096
#define ND     1280
#define NCTX   77
#define NKP    80          // padded keys
#define NCDIM  2048
#define NADIM  768
#define NHEADS 20
#define NHD    64
#define MQ     (NB*NS)     // 32768
#define MKV    616
#define MKV_PAD 640
#define KVSPLIT 3

// ---------------- scratch (device globals; no allocation allowed) -----------
__device__ __half g_hs_h[MQ * ND];           // fp16(hidden_states)
__device__ __half g_q[MQ * ND];              // Q projection (fp16)
__device__ __half g_attn[MQ * ND];           // attention out (fp16)
__device__ __half g_enc_h[MKV_PAD * NCDIM];  // fp16(encoder), padded rows
__device__ __half g_k[MKV * ND];             // K fp16 (0.125 folded into wkt)
__device__ __half g_v[MKV * ND];
__device__ __half g_wqt[ND * ND];            // W^T fp16  [N,K]
__device__ __half g_wot[ND * ND];
__device__ __half g_wkt[ND * NCDIM];         // includes 0.125 scale
__device__ __half g_wvt[ND * NCDIM];
__device__ float  g_kvpart[2 * KVSPLIT * MKV_PAD * ND];  // split-K partials
__device__ float  g_tip[NB * ND];
__device__ float  g_bias[NB * ND];

__device__ __forceinline__ void mma_f16(float* d, const uint32_t* a, const uint32_t* b) {
    asm volatile("mma.sync.aligned.m16n8k16.row.col.f32.f16.f16.f32 "
                 "{%0,%1,%2,%3}, {%4,%5,%6,%7}, {%8,%9}, {%0,%1,%2,%3};"
                 : "+f"(d[0]), "+f"(d[1]), "+f"(d[2]), "+f"(d[3])
                 : "r"(a[0]), "r"(a[1]), "r"(a[2]), "r"(a[3]),
                   "r"(b[0]), "r"(b[1]));
}
__device__ __forceinline__ void ldsm4(uint32_t* r, uint32_t addr) {
    asm volatile("ldmatrix.sync.aligned.m8n8.x4.shared.b16 {%0,%1,%2,%3}, [%4];"
                 : "=r"(r[0]), "=r"(r[1]), "=r"(r[2]), "=r"(r[3]) : "r"(addr));
}
__device__ __forceinline__ uint32_t pack_h2(float lo, float hi) {
    __half2 t = __floats2half2_rn(lo, hi);
    return *reinterpret_cast<uint32_t*>(&t);
}

// ---------------- shared GEMM core pieces ------------------------------------
#define BK 64
#define ATILE 16384                     // 128 rows x 128B
#define STAGE_BYTES (2 * ATILE)
#define GEMM_SMEM (2 * STAGE_BYTES)     // 64 KB

#define LOAD_STAGE(t) do {                                                    \
        uint32_t st_ = sbase + (uint32_t)((t) & 1) * STAGE_BYTES;             \
        int k0_ = (t) * BK;                                                   \
        _Pragma("unroll")                                                     \
        for (int i_ = 0; i_ < 8; i_++) {                                      \
            asm volatile("cp.async.cg.shared.global [%0], [%1], 16;"          \
                :: "r"(st_ + so0 + i_ * 2048u), "l"(gA0 + k0_ + i_ * gstep)); \
            asm volatile("cp.async.cg.shared.global [%0], [%1], 16;"          \
                :: "r"(st_ + ATILE + so0 + i_ * 2048u),                       \
                   "l"(gB0 + k0_ + i_ * gstep));                              \
        }                                                                     \
        asm volatile("cp.async.commit_group;" ::: "memory");                  \
    } while (0)

#define GEMM_BODY_MAIN()                                                      \
    const int g = lane >> 3, rin = lane & 7;                                  \
    const int ac = g >> 1;                                                    \
    uint32_t aoff[4], amask[4];                                               \
    _Pragma("unroll")                                                         \
    for (int mf = 0; mf < 4; mf++) {                                          \
        int ar = warp_m * 64 + mf * 16 + (g & 1) * 8 + rin;                   \
        aoff[mf] = (uint32_t)ar * 128;                                        \
        amask[mf] = (uint32_t)(ar & 7);                                       \
    }                                                                         \
    const int bc = g & 1;                                                     \
    uint32_t boff[4], bmask[4];                                               \
    _Pragma("unroll")                                                         \
    for (int p = 0; p < 4; p++) {                                             \
        int br = warp_n * 64 + (2 * p + (g >> 1)) * 8 + rin;                  \
        boff[p] = ATILE + (uint32_t)br * 128;                                 \
        bmask[p] = (uint32_t)(br & 7);                                        \
    }                                                                         \
    float acc[4][8][4];                                                       \
    _Pragma("unroll")                                                         \
    for (int mf = 0; mf < 4; mf++)                                            \
        _Pragma("unroll")                                                     \
        for (int nf = 0; nf < 8; nf++)                                        \
            _Pragma("unroll")                                                 \
            for (int j = 0; j < 4; j++) acc[mf][nf][j] = 0.f;                 \
    LOAD_STAGE(0);                                                            \
    LOAD_STAGE(1);                                                            \
    for (int s = 0; s < S; s++) {                                             \
        asm volatile("cp.async.wait_group %0;" :: "n"(1) : "memory");         \
        __syncthreads();                                                      \
        const uint32_t stg = sbase + (uint32_t)(s & 1) * STAGE_BYTES;         \
        _Pragma("unroll")                                                     \
        for (int kk = 0; kk < 4; kk++) {                                      \
            uint32_t bfr[4][4];                                               \
            _Pragma("unroll")                                                 \
            for (int p = 0; p < 4; p++)                                       \
                ldsm4(bfr[p], stg + boff[p] +                                 \
                      ((((uint32_t)(2 * kk + bc)) ^ bmask[p]) << 4));         \
            _Pragma("unroll")                                                 \
            for (int mf = 0; mf < 4; mf++) {                                  \
                uint32_t a[4];                                                \
                ldsm4(a, stg + aoff[mf] +                                     \
                      ((((uint32_t)(2 * kk + ac)) ^ amask[mf]) << 4));        \
                _Pragma("unroll")                                             \
                for (int nf = 0; nf < 8; nf++)                                \
                    mma_f16(acc[mf][nf], a, &bfr[nf >> 1][(nf & 1) * 2]);     \
            }                                                                 \
        }                                                                     \
        __syncthreads();                                                      \
        if (s + 2 < S) LOAD_STAGE(s + 2);                                     \
        else asm volatile("cp.async.commit_group;" ::: "memory");             \
    }

// ---------------- main fp16 GEMM (Q-proj / O-proj) ---------------------------
template <typename OutT>
__global__ __launch_bounds__(128, 3)
void h16_gemm(const __half* __restrict__ A, const __half* __restrict__ Bt,
              OutT* __restrict__ C, int M, int K, int Ntot,
              const float* __restrict__ bias, int rows_per_batch)
{
    extern __shared__ char smem[];
    const int tid = threadIdx.x;
    const int wid = tid >> 5, lane = tid & 31;
    const int warp_m = wid & 1;
    const int warp_n = wid >> 1;
    const int bm = blockIdx.y * 128;
    const int bn = blockIdx.x * 128;
    const int S = K / BK;
    const uint32_t sbase = (uint32_t)__cvta_generic_to_shared(smem);

    const int lrow = tid >> 3;
    const int lc16 = tid & 7;
    const __half* gA0 = A  + (size_t)(bm + lrow) * K + lc16 * 8;
    const __half* gB0 = Bt + (size_t)(bn + lrow) * K + lc16 * 8;
    const size_t gstep = (size_t)16 * K;
    const uint32_t so0 = (uint32_t)lrow * 128 + (uint32_t)((lc16 ^ (lrow & 7)) << 4);

    GEMM_BODY_MAIN()

#pragma unroll
    for (int mf = 0; mf < 4; mf++) {
        int r0 = bm + warp_m * 64 + mf * 16 + (lane >> 2);
#pragma unroll
        for (int half_ = 0; half_ < 2; half_++) {
            int r = r0 + half_ * 8;
            if (r >= M) continue;
            OutT* crow = C + (size_t)r * Ntot + bn + warp_n * 64;
            const float* brow = bias
                ? bias + (size_t)(r / rows_per_batch) * Ntot + bn + warp_n * 64
                : nullptr;
#pragma unroll
            for (int nf = 0; nf < 8; nf++) {
                int cc = nf * 8 + (lane & 3) * 2;
                float ox = acc[mf][nf][half_ * 2 + 0];
                float oy = acc[mf][nf][half_ * 2 + 1];
                if (bias) { ox += brow[cc]; oy += brow[cc + 1]; }
                if constexpr (sizeof(OutT) == 2) {
                    *(__half2*)(crow + cc) = __floats2half2_rn(ox, oy);
                } else {
                    *(float2*)(crow + cc) = make_float2(ox, oy);
                }
            }
        }
    }
}

// ---------------- split-K KV projection --------------------------------------
__global__ __launch_bounds__(128, 3)
void kv_gemm(const __half* __restrict__ enc_h, const __half* __restrict__ wkt,
             const __half* __restrict__ wvt, float* __restrict__ part)
{
    extern __shared__ char smem[];
    const int kv = blockIdx.z & 1;
    const int sp = blockIdx.z >> 1;
    const int s_begin = (sp == 0) ? 0 : (sp == 1 ? 11 : 22);
    const int S = (sp == 2) ? 10 : 11;
    const __half* Bt = kv ? wvt : wkt;

    const int tid = threadIdx.x;
    const int wid = tid >> 5, lane = tid & 31;
    const int warp_m = wid & 1;
    const int warp_n = wid >> 1;
    const int bm = blockIdx.y * 128;
    const int bn = blockIdx.x * 128;
    const uint32_t sbase = (uint32_t)__cvta_generic_to_shared(smem);

    const int lrow = tid >> 3;
    const int lc16 = tid & 7;
    const __half* gA0 = enc_h + (size_t)(bm + lrow) * NCDIM + s_begin * BK + lc16 * 8;
    const __half* gB0 = Bt    + (size_t)(bn + lrow) * NCDIM + s_begin * BK + lc16 * 8;
    const size_t gstep = (size_t)16 * NCDIM;
    const uint32_t so0 = (uint32_t)lrow * 128 + (uint32_t)((lc16 ^ (lrow & 7)) << 4);

    GEMM_BODY_MAIN()

    float* base = part + ((size_t)(kv * KVSPLIT + sp)) * MKV_PAD * ND;
#pragma unroll
    for (int mf = 0; mf < 4; mf++) {
        int r0 = bm + warp_m * 64 + mf * 16 + (lane >> 2);
#pragma unroll
        for (int half_ = 0; half_ < 2; half_++) {
            int r = r0 + half_ * 8;
            float* crow = base + (size_t)r * ND + bn + warp_n * 64;
#pragma unroll
            for (int nf = 0; nf < 8; nf++) {
                int cc = nf * 8 + (lane & 3) * 2;
                *(float2*)(crow + cc) =
                    make_float2(acc[mf][nf][half_ * 2 + 0],
                                acc[mf][nf][half_ * 2 + 1]);
            }
        }
    }
}

// sum the split partials -> fp16 K/V buffers
__global__ void kv_reduce(const float* __restrict__ part,
                          __half* __restrict__ kbuf, __half* __restrict__ vbuf)
{
    long i = (long)blockIdx.x * blockDim.x + threadIdx.x;
    const long n4 = (long)2 * MKV * ND / 4;
    if (i >= n4) return;
    long e = i * 4;
    int kv = (int)(e / ((long)MKV * ND));
    long rem = e - (long)kv * MKV * ND;
    const float* b = part + (size_t)kv * KVSPLIT * MKV_PAD * ND + rem;
    float4 p0 = *(const float4*)(b);
    float4 p1 = *(const float4*)(b + (size_t)MKV_PAD * ND);
    float4 p2 = *(const float4*)(b + (size_t)2 * MKV_PAD * ND);
    __half* o = (kv ? vbuf : kbuf) + rem;
    *(__half2*)(o)     = __floats2half2_rn(p0.x + p1.x + p2.x, p0.y + p1.y + p2.y);
    *(__half2*)(o + 2) = __floats2half2_rn(p0.z + p1.z + p2.z, p0.w + p1.w + p2.w);
}

// ---------------- persistent attention: 8 q-tiles per CTA --------------------
// grid (4, 20, 8) = 640 CTAs, 256 threads. K/V loaded once; Q tiles streamed
// via 2-deep cp.async double buffer. Register-resident P.
#define QT 8
#define VPITCH 88
#define A_QS 0
#define A_KS (2 * 128 * 64)                   // 16384 (after Q double buffer)
#define A_VT (A_KS + NKP * 64)                // 21504
#define ATTN_SMEM ((A_VT + 64 * VPITCH) * 2)  // 54272 B

__global__ __launch_bounds__(256, 2)
void attn_mma_kernel(const __half* __restrict__ q, const __half* __restrict__ kbuf,
                     const __half* __restrict__ vbuf, __half* __restrict__ out)
{
    extern __shared__ __half smh[];
    __half* Qs = smh + A_QS;          // [2][128*64]
    __half* Ks = smh + A_KS;
    __half* Vt = smh + A_VT;

    const int b = blockIdx.z;
    const int h = blockIdx.y;
    const int qc0 = blockIdx.x * (QT * 128);
    const int tid = threadIdx.x;
    const int warp = tid >> 5, lane = tid & 31;
    const int rb = lane >> 2, cb = lane & 3;

    // K/V fills (once per CTA)
    for (int i = tid; i < NKP * 8; i += 256) {
        int r = i >> 3, c = i & 7;
        uint4 t = make_uint4(0u, 0u, 0u, 0u);
        if (r < NCTX)
            t = *(const uint4*)&kbuf[((size_t)(b * NCTX + r)) * ND + h * NHD + c * 8];
        *(uint4*)&Ks[r * 64 + ((c ^ (r & 7)) << 3)] = t;
    }
    for (int i = tid; i < NKP * NHD; i += 256) {
        int r = i >> 6, d = i & 63;
        __half t = (r < NCTX)
            ? vbuf[((size_t)(b * NCTX + r)) * ND + h * NHD + d] : __half(0.f);
        Vt[d * VPITCH + r] = t;
    }

    // per-thread Q prefetch addressing: 4 chunks of 16B
    const uint32_t sbase = (uint32_t)__cvta_generic_to_shared(smh);
    uint32_t qdst[4];
    const __half* qsrc[4];
#pragma unroll
    for (int j = 0; j < 4; j++) {
        int idx = tid + j * 256;          // 0..1023
        int r = idx >> 3, c = idx & 7;
        qdst[j] = sbase + 2u * ((uint32_t)r * 64 + ((c ^ (r & 7)) << 3));
        qsrc[j] = q + ((size_t)(b * NS + qc0 + r)) * ND + h * NHD + c * 8;
    }
#define Q_PREFETCH(t) do {                                                    \
        uint32_t bufo = (uint32_t)((t) & 1) * 16384u;                         \
        const __half* srco_ = qsrc[0] + (size_t)(t) * 128 * ND;               \
        _Pragma("unroll")                                                     \
        for (int j_ = 0; j_ < 4; j_++)                                        \
            asm volatile("cp.async.cg.shared.global [%0], [%1], 16;"          \
                :: "r"(qdst[j_] + bufo),                                      \
                   "l"(qsrc[j_] + (size_t)(t) * 128 * ND));                   \
        asm volatile("cp.async.commit_group;" ::: "memory");                  \
    } while (0)

    Q_PREFETCH(0);

    const int qrow = warp * 16 + rb;

    for (int t = 0; t < QT; t++) {
        if (t + 1 < QT) {
            Q_PREFETCH(t + 1);
            asm volatile("cp.async.wait_group 1;" ::: "memory");
        } else {
            asm volatile("cp.async.wait_group 0;" ::: "memory");
        }
        __syncthreads();   // tile t visible (also covers K/V STS on t=0)

        const __half* Qb = Qs + (t & 1) * (128 * 64);
        const int q0 = qc0 + t * 128;

        // ---- S = Q K^T ----
        float sacc[10][4];
#pragma unroll
        for (int nf = 0; nf < 10; nf++)
#pragma unroll
            for (int j = 0; j < 4; j++) sacc[nf][j] = 0.f;

#pragma unroll
        for (int kk = 0; kk < 4; kk++) {
            uint32_t a[4];
            {
                uint32_t a0 = (uint32_t)qrow * 128 + (((2 * kk) ^ rb) << 4) + cb * 4;
                const char* base = (const char*)Qb;
                a[0] = *(const uint32_t*)(base + a0);
                a[1] = *(const uint32_t*)(base + a0 + 1024);
                a[2] = *(const uint32_t*)(base + (a0 ^ 16));
                a[3] = *(const uint32_t*)(base + ((a0 + 1024) ^ 16));
            }
#pragma unroll
            for (int nf = 0; nf < 10; nf++) {
                int n = nf * 8 + rb;
                uint32_t b0 = (uint32_t)n * 128 + (((2 * kk) ^ rb) << 4) + cb * 4;
                const char* base = (const char*)Ks;
                uint32_t bf[2];
                bf[0] = *(const uint32_t*)(base + b0);
                bf[1] = *(const uint32_t*)(base + (b0 ^ 16));
                mma_f16(sacc[nf], a, bf);
            }
        }

        // mask padded keys (cols 77..79 in nf=9)
        if (2 * cb >= 5)     { sacc[9][0] = -1e30f; sacc[9][2] = -1e30f; }
        if (2 * cb + 1 >= 5) { sacc[9][1] = -1e30f; sacc[9][3] = -1e30f; }

        // ---- softmax (register-resident P) ----
        float m0 = -1e30f, m1 = -1e30f;
#pragma unroll
        for (int nf = 0; nf < 10; nf++) {
            m0 = fmaxf(m0, fmaxf(sacc[nf][0], sacc[nf][1]));
            m1 = fmaxf(m1, fmaxf(sacc[nf][2], sacc[nf][3]));
        }
        m0 = fmaxf(m0, __shfl_xor_sync(0xFFFFFFFF, m0, 1));
        m0 = fmaxf(m0, __shfl_xor_sync(0xFFFFFFFF, m0, 2));
        m1 = fmaxf(m1, __shfl_xor_sync(0xFFFFFFFF, m1, 1));
        m1 = fmaxf(m1, __shfl_xor_sync(0xFFFFFFFF, m1, 2));

        float l0 = 0.f, l1 = 0.f;
        uint32_t pfrag[10][2];
#pragma unroll
        for (int nf = 0; nf < 10; nf++) {
            float p0 = __expf(sacc[nf][0] - m0);
            float p1 = __expf(sacc[nf][1] - m0);
            float p2 = __expf(sacc[nf][2] - m1);
            float p3 = __expf(sacc[nf][3] - m1);
            l0 += p0 + p1; l1 += p2 + p3;
            pfrag[nf][0] = pack_h2(p0, p1);
            pfrag[nf][1] = pack_h2(p2, p3);
        }
        l0 += __shfl_xor_sync(0xFFFFFFFF, l0, 1);
        l0 += __shfl_xor_sync(0xFFFFFFFF, l0, 2);
        l1 += __shfl_xor_sync(0xFFFFFFFF, l1, 1);
        l1 += __shfl_xor_sync(0xFFFFFFFF, l1, 2);

        // ---- O = P · Vt^T ----
        float oacc[8][4];
#pragma unroll
        for (int nf = 0; nf < 8; nf++)
#pragma unroll
            for (int j = 0; j < 4; j++) oacc[nf][j] = 0.f;

#pragma unroll
        for (int kk = 0; kk < 5; kk++) {
            uint32_t a[4];
            a[0] = pfrag[2 * kk][0];
            a[1] = pfrag[2 * kk][1];
            a[2] = pfrag[2 * kk + 1][0];
            a[3] = pfrag[2 * kk + 1][1];
#pragma unroll
            for (int nf = 0; nf < 8; nf++) {
                int n = nf * 8 + rb;
                uint32_t bf[2];
                bf[0] = *(const uint32_t*)&Vt[n * VPITCH + kk * 16 + 2 * cb];
                bf[1] = *(const uint32_t*)&Vt[n * VPITCH + kk * 16 + 8 + 2 * cb];
                mma_f16(oacc[nf], a, bf);
            }
        }

        const float inv0 = 1.f / l0, inv1 = 1.f / l1;
        __half* o0 = &out[((size_t)(b * NS + q0 + qrow)) * ND + h * NHD];
        __half* o1 = o0 + (size_t)8 * ND;
#pragma unroll
        for (int nf = 0; nf < 8; nf++) {
            int cc = nf * 8 + 2 * cb;
            *(__half2*)(o0 + cc) = __floats2half2_rn(oacc[nf][0] * inv0, oacc[nf][1] * inv0);
            *(__half2*)(o1 + cc) = __floats2half2_rn(oacc[nf][2] * inv1, oacc[nf][3] * inv1);
        }

        __syncthreads();   // all reads of Qs[t&1] done before its next overwrite
    }
#undef Q_PREFETCH
}

// ---------------- preprocessing ---------------------------------------------
__global__ void f2h_copy(const float4* __restrict__ in, __half2* __restrict__ out, long n4)
{
    long i = (long)blockIdx.x * blockDim.x + threadIdx.x;
    if (i < n4) {
        float4 v = in[i];
        out[i * 2]     = __floats2half2_rn(v.x, v.y);
        out[i * 2 + 1] = __floats2half2_rn(v.z, v.w);
    }
}

__global__ void f2h_pad_enc(const float* __restrict__ enc, __half* __restrict__ out)
{
    long i = (long)blockIdx.x * blockDim.x + threadIdx.x;
    if (i < (long)MKV_PAD * NCDIM) {
        long row = i / NCDIM;
        out[i] = (row < MKV) ? __float2half_rn(enc[i]) : __half(0.f);
    }
}

// all four weight transposes in one launch (z selects the matrix)
__global__ void transpose_all_kernel(const float* __restrict__ Wq, const float* __restrict__ Wk,
                                     const float* __restrict__ Wv, const float* __restrict__ Wo,
                                     __half* __restrict__ wqt, __half* __restrict__ wkt,
                                     __half* __restrict__ wvt, __half* __restrict__ wot)
{
    const float* W; __half* Wt; int K; float scale = 1.f;
    switch (blockIdx.z) {
        case 0:  W = Wq; Wt = wqt; K = ND;    break;
        case 1:  W = Wk; Wt = wkt; K = NCDIM; scale = 0.125f; break;
        case 2:  W = Wv; Wt = wvt; K = NCDIM; break;
        default: W = Wo; Wt = wot; K = ND;    break;
    }
    int k0 = blockIdx.y * 32, n0 = blockIdx.x * 32;
    if (k0 >= K) return;
    __shared__ float t[32][33];
    int x = threadIdx.x, y = threadIdx.y;
#pragma unroll
    for (int i = 0; i < 32; i += 8)
        t[y + i][x] = W[(size_t)(k0 + y + i) * ND + n0 + x];
    __syncthreads();
#pragma unroll
    for (int i = 0; i < 32; i += 8)
        Wt[(size_t)(n0 + y + i) * K + k0 + x] = __float2half_rn(t[x][y + i] * scale);
}

// ---------------- adapter branch (batch-shared weight reads) ----------------
__global__ void adapter1_kernel(const float* __restrict__ ad,
                                const float* __restrict__ Wva,
                                float* __restrict__ tip)
{
    __shared__ float ad_s[NB * NADIM];
    __shared__ float red[16][8][NB];
    const int tid = threadIdx.x;
    const int jj = tid & 7, ks = tid >> 3;
    const int j = blockIdx.x * 8 + jj;
    for (int i = tid; i < NB * NADIM; i += 128) ad_s[i] = ad[i];
    __syncthreads();
    float s[NB];
#pragma unroll
    for (int b = 0; b < NB; b++) s[b] = 0.f;
#pragma unroll 4
    for (int a = ks; a < NADIM; a += 16) {
        float w = Wva[(size_t)a * ND + j];
#pragma unroll
        for (int b = 0; b < NB; b++) s[b] += ad_s[b * NADIM + a] * w;
    }
#pragma unroll
    for (int b = 0; b < NB; b++) red[ks][jj][b] = s[b];
    __syncthreads();
    if (tid < 64) {
        int j2 = tid & 7, b = tid >> 3;
        float t = 0.f;
#pragma unroll
        for (int k = 0; k < 16; k++) t += red[k][j2][b];
        tip[b * ND + blockIdx.x * 8 + j2] = t;
    }
}

__global__ void adapter2_kernel(const float* __restrict__ tip,
                                const float* __restrict__ Wo,
                                const float* __restrict__ bo,
                                float* __restrict__ bias)
{
    __shared__ float tip_s[NB * ND];
    __shared__ float red[16][8][NB];
    const int tid = threadIdx.x;
    const int jj = tid & 7, ks = tid >> 3;
    const int j = blockIdx.x * 8 + jj;
    for (int i = tid; i < NB * ND; i += 128) tip_s[i] = tip[i];
    __syncthreads();
    float s[NB];
#pragma unroll
    for (int b = 0; b < NB; b++) s[b] = 0.f;
#pragma unroll 4
    for (int kk = ks; kk < ND; kk += 16) {
        float w = Wo[(size_t)kk * ND + j];
#pragma unroll
        for (int b = 0; b < NB; b++) s[b] += tip_s[b * ND + kk] * w;
    }
#pragma unroll
    for (int b = 0; b < NB; b++) red[ks][jj][b] = s[b];
    __syncthreads();
    if (tid < 64) {
        int j2 = tid & 7, b = tid >> 3;
        float t = 0.f;
#pragma unroll
        for (int k = 0; k < 16; k++) t += red[k][j2][b];
        int col = blockIdx.x * 8 + j2;
        bias[b * ND + col] = bo[col] + t;
    }
}

// ---------------------------------------------------------------------------
extern "C" void kernel_launch(void* const* d_in, const int* in_sizes, int n_in,
                              void* d_out, int out_size)
{
    const float* hs  = (const float*)d_in[0];
    const float* enc = (const float*)d_in[1];
    const float* ad  = (const float*)d_in[2];
    const float* Wq  = (const float*)d_in[3];
    const float* Wk  = (const float*)d_in[4];
    const float* Wv  = (const float*)d_in[5];
    // d_in[6] = Wk_adapter: unused (softmax over a single key is identically 1)
    const float* Wva = (const float*)d_in[7];
    const float* Wo  = (const float*)d_in[8];
    const float* bo  = (const float*)d_in[9];
    float* out = (float*)d_out;

    __half *hs_h, *q, *attn_o, *enc_h, *kbuf, *vbuf, *wqt, *wot, *wkt, *wvt;
    float *tip, *bias, *kvpart;
    cudaGetSymbolAddress((void**)&hs_h,   g_hs_h);
    cudaGetSymbolAddress((void**)&q,      g_q);
    cudaGetSymbolAddress((void**)&attn_o, g_attn);
    cudaGetSymbolAddress((void**)&enc_h,  g_enc_h);
    cudaGetSymbolAddress((void**)&kbuf,   g_k);
    cudaGetSymbolAddress((void**)&vbuf,   g_v);
    cudaGetSymbolAddress((void**)&wqt,    g_wqt);
    cudaGetSymbolAddress((void**)&wot,    g_wot);
    cudaGetSymbolAddress((void**)&wkt,    g_wkt);
    cudaGetSymbolAddress((void**)&wvt,    g_wvt);
    cudaGetSymbolAddress((void**)&kvpart, g_kvpart);
    cudaGetSymbolAddress((void**)&tip,    g_tip);
    cudaGetSymbolAddress((void**)&bias,   g_bias);

    cudaFuncSetAttribute(h16_gemm<float>,  cudaFuncAttributeMaxDynamicSharedMemorySize, GEMM_SMEM);
    cudaFuncSetAttribute(h16_gemm<__half>, cudaFuncAttributeMaxDynamicSharedMemorySize, GEMM_SMEM);
    cudaFuncSetAttribute(kv_gemm,          cudaFuncAttributeMaxDynamicSharedMemorySize, GEMM_SMEM);
    cudaFuncSetAttribute(attn_mma_kernel,  cudaFuncAttributeMaxDynamicSharedMemorySize, ATTN_SMEM);

    long n4 = (long)MQ * ND / 4;
    // ncu captures launch index 3 -> Q-projection GEMM placed there
    f2h_copy<<<(unsigned)((n4 + 255) / 256), 256>>>((const float4*)hs, (__half2*)hs_h, n4);   // 0
    f2h_pad_enc<<<(unsigned)(((long)MKV_PAD * NCDIM + 255) / 256), 256>>>(enc, enc_h);        // 1
    transpose_all_kernel<<<dim3(ND / 32, NCDIM / 32, 4), dim3(32, 8)>>>(                      // 2
        Wq, Wk, Wv, Wo, wqt, wkt, wvt, wot);
    h16_gemm<__half><<<dim3(ND / 128, MQ / 128), 128, GEMM_SMEM>>>(                           // 3 (profiled)
        hs_h, wqt, q, MQ, ND, ND, nullptr, 1);

    // split-K KV projections (0.125 folded into wkt)
    kv_gemm<<<dim3(ND / 128, MKV_PAD / 128, 2 * KVSPLIT), 128, GEMM_SMEM>>>(
        enc_h, wkt, wvt, kvpart);
    {
        long r4 = (long)2 * MKV * ND / 4;
        kv_reduce<<<(unsigned)((r4 + 255) / 256), 256>>>(kvpart, kbuf, vbuf);
    }

    adapter1_kernel<<<ND / 8, 128>>>(ad, Wva, tip);
    adapter2_kernel<<<ND / 8, 128>>>(tip, Wo, bo, bias);

    // persistent fp16 attention (8 q-tiles/CTA, cp.async Q streaming)
    attn_mma_kernel<<<dim3(NS / (128 * QT), NHEADS, NB), 256, ATTN_SMEM>>>(
        q, kbuf, vbuf, attn_o);

    // output projection + per-batch adapter bias (bo folded into bias), f32 out
    h16_gemm<float><<<dim3(ND / 128, MQ / 128), 128, GEMM_SMEM>>>(
        attn_o, wot, out, MQ, ND, ND, bias, NS);
}

// round 15
// speedup vs baseline: 1.1733x; 1.0043x over previous
#include <cuda_runtime.h>
#include <cuda_fp16.h>
#include <cstdint>
#include <math.h>

#define NB     8
#define NS     4096
#define ND     1280
#define NCTX   77
#define NKP    80          // padded keys
#define NCDIM  2048
#define NADIM  768
#define NHEADS 20
#define NHD    64
#define MQ     (NB*NS)     // 32768
#define MKV    616
#define MKV_PAD 640
#define KVSPLIT 4

// ---------------- scratch (device globals; no allocation allowed) -----------
__device__ __half g_hs_h[MQ * ND];           // fp16(hidden_states)
__device__ __half g_q[MQ * ND];              // Q projection (fp16)
__device__ __half g_attn[MQ * ND];           // attention out (fp16)
__device__ __half g_enc_h[MKV_PAD * NCDIM];  // fp16(encoder), padded rows
__device__ __half g_k[MKV * ND];             // K fp16 (0.125 folded into wkt)
__device__ __half g_v[MKV * ND];
__device__ __half g_wqt[ND * ND];            // W^T fp16  [N,K]
__device__ __half g_wot[ND * ND];
__device__ __half g_wkt[ND * NCDIM];         // includes 0.125 scale
__device__ __half g_wvt[ND * NCDIM];
__device__ float  g_kvpart[2 * KVSPLIT * MKV_PAD * ND];  // split-K partials
__device__ float  g_tip[NB * ND];
__device__ float  g_bias[NB * ND];

__device__ __forceinline__ void mma_f16(float* d, const uint32_t* a, const uint32_t* b) {
    asm volatile("mma.sync.aligned.m16n8k16.row.col.f32.f16.f16.f32 "
                 "{%0,%1,%2,%3}, {%4,%5,%6,%7}, {%8,%9}, {%0,%1,%2,%3};"
                 : "+f"(d[0]), "+f"(d[1]), "+f"(d[2]), "+f"(d[3])
                 : "r"(a[0]), "r"(a[1]), "r"(a[2]), "r"(a[3]),
                   "r"(b[0]), "r"(b[1]));
}
__device__ __forceinline__ void ldsm4(uint32_t* r, uint32_t addr) {
    asm volatile("ldmatrix.sync.aligned.m8n8.x4.shared.b16 {%0,%1,%2,%3}, [%4];"
                 : "=r"(r[0]), "=r"(r[1]), "=r"(r[2]), "=r"(r[3]) : "r"(addr));
}
__device__ __forceinline__ uint32_t pack_h2(float lo, float hi) {
    __half2 t = __floats2half2_rn(lo, hi);
    return *reinterpret_cast<uint32_t*>(&t);
}

// ---------------- shared GEMM core pieces ------------------------------------
#define BK 64
#define ATILE 16384                     // 128 rows x 128B
#define STAGE_BYTES (2 * ATILE)
#define GEMM_SMEM (2 * STAGE_BYTES)     // 64 KB

#define LOAD_STAGE(t) do {                                                    \
        uint32_t st_ = sbase + (uint32_t)((t) & 1) * STAGE_BYTES;             \
        int k0_ = (t) * BK;                                                   \
        _Pragma("unroll")                                                     \
        for (int i_ = 0; i_ < 8; i_++) {                                      \
            asm volatile("cp.async.cg.shared.global [%0], [%1], 16;"          \
                :: "r"(st_ + so0 + i_ * 2048u), "l"(gA0 + k0_ + i_ * gstep)); \
            asm volatile("cp.async.cg.shared.global [%0], [%1], 16;"          \
                :: "r"(st_ + ATILE + so0 + i_ * 2048u),                       \
                   "l"(gB0 + k0_ + i_ * gstep));                              \
        }                                                                     \
        asm volatile("cp.async.commit_group;" ::: "memory");                  \
    } while (0)

#define GEMM_BODY_MAIN()                                                      \
    const int g = lane >> 3, rin = lane & 7;                                  \
    const int ac = g >> 1;                                                    \
    uint32_t aoff[4], amask[4];                                               \
    _Pragma("unroll")                                                         \
    for (int mf = 0; mf < 4; mf++) {                                          \
        int ar = warp_m * 64 + mf * 16 + (g & 1) * 8 + rin;                   \
        aoff[mf] = (uint32_t)ar * 128;                                        \
        amask[mf] = (uint32_t)(ar & 7);                                       \
    }                                                                         \
    const int bc = g & 1;                                                     \
    uint32_t boff[4], bmask[4];                                               \
    _Pragma("unroll")                                                         \
    for (int p = 0; p < 4; p++) {                                             \
        int br = warp_n * 64 + (2 * p + (g >> 1)) * 8 + rin;                  \
        boff[p] = ATILE + (uint32_t)br * 128;                                 \
        bmask[p] = (uint32_t)(br & 7);                                        \
    }                                                                         \
    float acc[4][8][4];                                                       \
    _Pragma("unroll")                                                         \
    for (int mf = 0; mf < 4; mf++)                                            \
        _Pragma("unroll")                                                     \
        for (int nf = 0; nf < 8; nf++)                                        \
            _Pragma("unroll")                                                 \
            for (int j = 0; j < 4; j++) acc[mf][nf][j] = 0.f;                 \
    LOAD_STAGE(0);                                                            \
    LOAD_STAGE(1);                                                            \
    for (int s = 0; s < S; s++) {                                             \
        asm volatile("cp.async.wait_group %0;" :: "n"(1) : "memory");         \
        __syncthreads();                                                      \
        const uint32_t stg = sbase + (uint32_t)(s & 1) * STAGE_BYTES;         \
        _Pragma("unroll")                                                     \
        for (int kk = 0; kk < 4; kk++) {                                      \
            uint32_t bfr[4][4];                                               \
            _Pragma("unroll")                                                 \
            for (int p = 0; p < 4; p++)                                       \
                ldsm4(bfr[p], stg + boff[p] +                                 \
                      ((((uint32_t)(2 * kk + bc)) ^ bmask[p]) << 4));         \
            _Pragma("unroll")                                                 \
            for (int mf = 0; mf < 4; mf++) {                                  \
                uint32_t a[4];                                                \
                ldsm4(a, stg + aoff[mf] +                                     \
                      ((((uint32_t)(2 * kk + ac)) ^ amask[mf]) << 4));        \
                _Pragma("unroll")                                             \
                for (int nf = 0; nf < 8; nf++)                                \
                    mma_f16(acc[mf][nf], a, &bfr[nf >> 1][(nf & 1) * 2]);     \
            }                                                                 \
        }                                                                     \
        __syncthreads();                                                      \
        if (s + 2 < S) LOAD_STAGE(s + 2);                                     \
        else asm volatile("cp.async.commit_group;" ::: "memory");             \
    }

// ---------------- main fp16 GEMM (Q-proj / O-proj) ---------------------------
template <typename OutT>
__global__ __launch_bounds__(128, 3)
void h16_gemm(const __half* __restrict__ A, const __half* __restrict__ Bt,
              OutT* __restrict__ C, int M, int K, int Ntot,
              const float* __restrict__ bias, int rows_per_batch)
{
    extern __shared__ char smem[];
    const int tid = threadIdx.x;
    const int wid = tid >> 5, lane = tid & 31;
    const int warp_m = wid & 1;
    const int warp_n = wid >> 1;
    const int bm = blockIdx.y * 128;
    const int bn = blockIdx.x * 128;
    const int S = K / BK;
    const uint32_t sbase = (uint32_t)__cvta_generic_to_shared(smem);

    const int lrow = tid >> 3;
    const int lc16 = tid & 7;
    const __half* gA0 = A  + (size_t)(bm + lrow) * K + lc16 * 8;
    const __half* gB0 = Bt + (size_t)(bn + lrow) * K + lc16 * 8;
    const size_t gstep = (size_t)16 * K;
    const uint32_t so0 = (uint32_t)lrow * 128 + (uint32_t)((lc16 ^ (lrow & 7)) << 4);

    GEMM_BODY_MAIN()

#pragma unroll
    for (int mf = 0; mf < 4; mf++) {
        int r0 = bm + warp_m * 64 + mf * 16 + (lane >> 2);
#pragma unroll
        for (int half_ = 0; half_ < 2; half_++) {
            int r = r0 + half_ * 8;
            if (r >= M) continue;
            OutT* crow = C + (size_t)r * Ntot + bn + warp_n * 64;
            const float* brow = bias
                ? bias + (size_t)(r / rows_per_batch) * Ntot + bn + warp_n * 64
                : nullptr;
#pragma unroll
            for (int nf = 0; nf < 8; nf++) {
                int cc = nf * 8 + (lane & 3) * 2;
                float ox = acc[mf][nf][half_ * 2 + 0];
                float oy = acc[mf][nf][half_ * 2 + 1];
                if (bias) { ox += brow[cc]; oy += brow[cc + 1]; }
                if constexpr (sizeof(OutT) == 2) {
                    *(__half2*)(crow + cc) = __floats2half2_rn(ox, oy);
                } else {
                    *(float2*)(crow + cc) = make_float2(ox, oy);
                }
            }
        }
    }
}

// ---------------- split-K KV projection --------------------------------------
// grid (10, 5, 2*KVSPLIT): z = sp*2 + kv, 8 stages each. f32 partials.
__global__ __launch_bounds__(128, 3)
void kv_gemm(const __half* __restrict__ enc_h, const __half* __restrict__ wkt,
             const __half* __restrict__ wvt, float* __restrict__ part)
{
    extern __shared__ char smem[];
    const int kv = blockIdx.z & 1;
    const int sp = blockIdx.z >> 1;                  // 0..KVSPLIT-1
    const int s_begin = sp * 8;
    const int S = 8;
    const __half* Bt = kv ? wvt : wkt;

    const int tid = threadIdx.x;
    const int wid = tid >> 5, lane = tid & 31;
    const int warp_m = wid & 1;
    const int warp_n = wid >> 1;
    const int bm = blockIdx.y * 128;
    const int bn = blockIdx.x * 128;
    const uint32_t sbase = (uint32_t)__cvta_generic_to_shared(smem);

    const int lrow = tid >> 3;
    const int lc16 = tid & 7;
    const __half* gA0 = enc_h + (size_t)(bm + lrow) * NCDIM + s_begin * BK + lc16 * 8;
    const __half* gB0 = Bt    + (size_t)(bn + lrow) * NCDIM + s_begin * BK + lc16 * 8;
    const size_t gstep = (size_t)16 * NCDIM;
    const uint32_t so0 = (uint32_t)lrow * 128 + (uint32_t)((lc16 ^ (lrow & 7)) << 4);

    GEMM_BODY_MAIN()

    float* base = part + ((size_t)(kv * KVSPLIT + sp)) * MKV_PAD * ND;
#pragma unroll
    for (int mf = 0; mf < 4; mf++) {
        int r0 = bm + warp_m * 64 + mf * 16 + (lane >> 2);
#pragma unroll
        for (int half_ = 0; half_ < 2; half_++) {
            int r = r0 + half_ * 8;
            float* crow = base + (size_t)r * ND + bn + warp_n * 64;
#pragma unroll
            for (int nf = 0; nf < 8; nf++) {
                int cc = nf * 8 + (lane & 3) * 2;
                *(float2*)(crow + cc) =
                    make_float2(acc[mf][nf][half_ * 2 + 0],
                                acc[mf][nf][half_ * 2 + 1]);
            }
        }
    }
}

// sum the split partials -> fp16 K/V buffers
__global__ void kv_reduce(const float* __restrict__ part,
                          __half* __restrict__ kbuf, __half* __restrict__ vbuf)
{
    long i = (long)blockIdx.x * blockDim.x + threadIdx.x;
    const long n4 = (long)2 * MKV * ND / 4;
    if (i >= n4) return;
    long e = i * 4;
    int kv = (int)(e / ((long)MKV * ND));
    long rem = e - (long)kv * MKV * ND;
    const float* b = part + (size_t)kv * KVSPLIT * MKV_PAD * ND + rem;
    float4 p0 = *(const float4*)(b);
    float4 p1 = *(const float4*)(b + (size_t)MKV_PAD * ND);
    float4 p2 = *(const float4*)(b + (size_t)2 * MKV_PAD * ND);
    float4 p3 = *(const float4*)(b + (size_t)3 * MKV_PAD * ND);
    __half* o = (kv ? vbuf : kbuf) + rem;
    *(__half2*)(o)     = __floats2half2_rn((p0.x + p1.x) + (p2.x + p3.x),
                                           (p0.y + p1.y) + (p2.y + p3.y));
    *(__half2*)(o + 2) = __floats2half2_rn((p0.z + p1.z) + (p2.z + p3.z),
                                           (p0.w + p1.w) + (p2.w + p3.w));
}

// ---------------- persistent attention: 8 q-tiles per CTA --------------------
#define QT 8
#define VPITCH 88
#define A_QS 0
#define A_KS (2 * 128 * 64)                   // 16384 (after Q double buffer)
#define A_VT (A_KS + NKP * 64)                // 21504
#define ATTN_SMEM ((A_VT + 64 * VPITCH) * 2)  // 54272 B

__global__ __launch_bounds__(256, 2)
void attn_mma_kernel(const __half* __restrict__ q, const __half* __restrict__ kbuf,
                     const __half* __restrict__ vbuf, __half* __restrict__ out)
{
    extern __shared__ __half smh[];
    __half* Qs = smh + A_QS;          // [2][128*64]
    __half* Ks = smh + A_KS;
    __half* Vt = smh + A_VT;

    const int b = blockIdx.z;
    const int h = blockIdx.y;
    const int qc0 = blockIdx.x * (QT * 128);
    const int tid = threadIdx.x;
    const int warp = tid >> 5, lane = tid & 31;
    const int rb = lane >> 2, cb = lane & 3;

    // per-thread Q prefetch addressing: 4 chunks of 16B
    const uint32_t sbase = (uint32_t)__cvta_generic_to_shared(smh);
    uint32_t qdst[4];
    const __half* qsrc[4];
#pragma unroll
    for (int j = 0; j < 4; j++) {
        int idx = tid + j * 256;          // 0..1023
        int r = idx >> 3, c = idx & 7;
        qdst[j] = sbase + 2u * ((uint32_t)r * 64 + ((c ^ (r & 7)) << 3));
        qsrc[j] = q + ((size_t)(b * NS + qc0 + r)) * ND + h * NHD + c * 8;
    }
#define Q_PREFETCH(t) do {                                                    \
        uint32_t bufo = (uint32_t)((t) & 1) * 16384u;                         \
        _Pragma("unroll")                                                     \
        for (int j_ = 0; j_ < 4; j_++)                                        \
            asm volatile("cp.async.cg.shared.global [%0], [%1], 16;"          \
                :: "r"(qdst[j_] + bufo),                                      \
                   "l"(qsrc[j_] + (size_t)(t) * 128 * ND));                   \
        asm volatile("cp.async.commit_group;" ::: "memory");                  \
    } while (0)

    // prefetch first Q tile before the K/V fills so it overlaps them
    Q_PREFETCH(0);

    // K/V fills (once per CTA)
    for (int i = tid; i < NKP * 8; i += 256) {
        int r = i >> 3, c = i & 7;
        uint4 t = make_uint4(0u, 0u, 0u, 0u);
        if (r < NCTX)
            t = *(const uint4*)&kbuf[((size_t)(b * NCTX + r)) * ND + h * NHD + c * 8];
        *(uint4*)&Ks[r * 64 + ((c ^ (r & 7)) << 3)] = t;
    }
    for (int i = tid; i < NKP * NHD; i += 256) {
        int r = i >> 6, d = i & 63;
        __half t = (r < NCTX)
            ? vbuf[((size_t)(b * NCTX + r)) * ND + h * NHD + d] : __half(0.f);
        Vt[d * VPITCH + r] = t;
    }

    const int qrow = warp * 16 + rb;

    for (int t = 0; t < QT; t++) {
        if (t + 1 < QT) {
            Q_PREFETCH(t + 1);
            asm volatile("cp.async.wait_group 1;" ::: "memory");
        } else {
            asm volatile("cp.async.wait_group 0;" ::: "memory");
        }
        __syncthreads();   // tile t visible (also covers K/V STS on t=0)

        const __half* Qb = Qs + (t & 1) * (128 * 64);
        const int q0 = qc0 + t * 128;

        // ---- S = Q K^T ----
        float sacc[10][4];
#pragma unroll
        for (int nf = 0; nf < 10; nf++)
#pragma unroll
            for (int j = 0; j < 4; j++) sacc[nf][j] = 0.f;

#pragma unroll
        for (int kk = 0; kk < 4; kk++) {
            uint32_t a[4];
            {
                uint32_t a0 = (uint32_t)qrow * 128 + (((2 * kk) ^ rb) << 4) + cb * 4;
                const char* base = (const char*)Qb;
                a[0] = *(const uint32_t*)(base + a0);
                a[1] = *(const uint32_t*)(base + a0 + 1024);
                a[2] = *(const uint32_t*)(base + (a0 ^ 16));
                a[3] = *(const uint32_t*)(base + ((a0 + 1024) ^ 16));
            }
#pragma unroll
            for (int nf = 0; nf < 10; nf++) {
                int n = nf * 8 + rb;
                uint32_t b0 = (uint32_t)n * 128 + (((2 * kk) ^ rb) << 4) + cb * 4;
                const char* base = (const char*)Ks;
                uint32_t bf[2];
                bf[0] = *(const uint32_t*)(base + b0);
                bf[1] = *(const uint32_t*)(base + (b0 ^ 16));
                mma_f16(sacc[nf], a, bf);
            }
        }

        // mask padded keys (cols 77..79 in nf=9)
        if (2 * cb >= 5)     { sacc[9][0] = -1e30f; sacc[9][2] = -1e30f; }
        if (2 * cb + 1 >= 5) { sacc[9][1] = -1e30f; sacc[9][3] = -1e30f; }

        // ---- softmax (register-resident P) ----
        float m0 = -1e30f, m1 = -1e30f;
#pragma unroll
        for (int nf = 0; nf < 10; nf++) {
            m0 = fmaxf(m0, fmaxf(sacc[nf][0], sacc[nf][1]));
            m1 = fmaxf(m1, fmaxf(sacc[nf][2], sacc[nf][3]));
        }
        m0 = fmaxf(m0, __shfl_xor_sync(0xFFFFFFFF, m0, 1));
        m0 = fmaxf(m0, __shfl_xor_sync(0xFFFFFFFF, m0, 2));
        m1 = fmaxf(m1, __shfl_xor_sync(0xFFFFFFFF, m1, 1));
        m1 = fmaxf(m1, __shfl_xor_sync(0xFFFFFFFF, m1, 2));

        float l0 = 0.f, l1 = 0.f;
        uint32_t pfrag[10][2];
#pragma unroll
        for (int nf = 0; nf < 10; nf++) {
            float p0 = __expf(sacc[nf][0] - m0);
            float p1 = __expf(sacc[nf][1] - m0);
            float p2 = __expf(sacc[nf][2] - m1);
            float p3 = __expf(sacc[nf][3] - m1);
            l0 += p0 + p1; l1 += p2 + p3;
            pfrag[nf][0] = pack_h2(p0, p1);
            pfrag[nf][1] = pack_h2(p2, p3);
        }
        l0 += __shfl_xor_sync(0xFFFFFFFF, l0, 1);
        l0 += __shfl_xor_sync(0xFFFFFFFF, l0, 2);
        l1 += __shfl_xor_sync(0xFFFFFFFF, l1, 1);
        l1 += __shfl_xor_sync(0xFFFFFFFF, l1, 2);

        // ---- O = P · Vt^T ----
        float oacc[8][4];
#pragma unroll
        for (int nf = 0; nf < 8; nf++)
#pragma unroll
            for (int j = 0; j < 4; j++) oacc[nf][j] = 0.f;

#pragma unroll
        for (int kk = 0; kk < 5; kk++) {
            uint32_t a[4];
            a[0] = pfrag[2 * kk][0];
            a[1] = pfrag[2 * kk][1];
            a[2] = pfrag[2 * kk + 1][0];
            a[3] = pfrag[2 * kk + 1][1];
#pragma unroll
            for (int nf = 0; nf < 8; nf++) {
                int n = nf * 8 + rb;
                uint32_t bf[2];
                bf[0] = *(const uint32_t*)&Vt[n * VPITCH + kk * 16 + 2 * cb];
                bf[1] = *(const uint32_t*)&Vt[n * VPITCH + kk * 16 + 8 + 2 * cb];
                mma_f16(oacc[nf], a, bf);
            }
        }

        const float inv0 = 1.f / l0, inv1 = 1.f / l1;
        __half* o0 = &out[((size_t)(b * NS + q0 + qrow)) * ND + h * NHD];
        __half* o1 = o0 + (size_t)8 * ND;
#pragma unroll
        for (int nf = 0; nf < 8; nf++) {
            int cc = nf * 8 + 2 * cb;
            *(__half2*)(o0 + cc) = __floats2half2_rn(oacc[nf][0] * inv0, oacc[nf][1] * inv0);
            *(__half2*)(o1 + cc) = __floats2half2_rn(oacc[nf][2] * inv1, oacc[nf][3] * inv1);
        }

        __syncthreads();   // all reads of Qs[t&1] done before its next overwrite
    }
#undef Q_PREFETCH
}

// ---------------- preprocessing: hs + enc fp32->fp16 in one launch -----------
__global__ void f2h_all(const float4* __restrict__ hs, __half2* __restrict__ hs_out,
                        const float* __restrict__ enc, __half* __restrict__ enc_out,
                        long n4_hs, long n4_enc)
{
    long i = (long)blockIdx.x * blockDim.x + threadIdx.x;
    if (i < n4_hs) {
        float4 v = hs[i];
        hs_out[i * 2]     = __floats2half2_rn(v.x, v.y);
        hs_out[i * 2 + 1] = __floats2half2_rn(v.z, v.w);
    } else {
        long j = i - n4_hs;
        if (j < n4_enc) {
            long e = j * 4;
            long row = e / NCDIM;
            if (row < MKV) {
                float4 v = *(const float4*)(enc + e);
                *(__half2*)(enc_out + e)     = __floats2half2_rn(v.x, v.y);
                *(__half2*)(enc_out + e + 2) = __floats2half2_rn(v.z, v.w);
            } else {
                *(__half2*)(enc_out + e)     = __floats2half2_rn(0.f, 0.f);
                *(__half2*)(enc_out + e + 2) = __floats2half2_rn(0.f, 0.f);
            }
        }
    }
}

// all four weight transposes in one launch (z selects the matrix)
__global__ void transpose_all_kernel(const float* __restrict__ Wq, const float* __restrict__ Wk,
                                     const float* __restrict__ Wv, const float* __restrict__ Wo,
                                     __half* __restrict__ wqt, __half* __restrict__ wkt,
                                     __half* __restrict__ wvt, __half* __restrict__ wot)
{
    const float* W; __half* Wt; int K; float scale = 1.f;
    switch (blockIdx.z) {
        case 0:  W = Wq; Wt = wqt; K = ND;    break;
        case 1:  W = Wk; Wt = wkt; K = NCDIM; scale = 0.125f; break;
        case 2:  W = Wv; Wt = wvt; K = NCDIM; break;
        default: W = Wo; Wt = wot; K = ND;    break;
    }
    int k0 = blockIdx.y * 32, n0 = blockIdx.x * 32;
    if (k0 >= K) return;
    __shared__ float t[32][33];
    int x = threadIdx.x, y = threadIdx.y;
#pragma unroll
    for (int i = 0; i < 32; i += 8)
        t[y + i][x] = W[(size_t)(k0 + y + i) * ND + n0 + x];
    __syncthreads();
#pragma unroll
    for (int i = 0; i < 32; i += 8)
        Wt[(size_t)(n0 + y + i) * K + k0 + x] = __float2half_rn(t[x][y + i] * scale);
}

// ---------------- adapter branch (batch-shared weight reads) ----------------
__global__ void adapter1_kernel(const float* __restrict__ ad,
                                const float* __restrict__ Wva,
                                float* __restrict__ tip)
{
    __shared__ float ad_s[NB * NADIM];
    __shared__ float red[16][8][NB];
    const int tid = threadIdx.x;
    const int jj = tid & 7, ks = tid >> 3;
    const int j = blockIdx.x * 8 + jj;
    for (int i = tid; i < NB * NADIM; i += 128) ad_s[i] = ad[i];
    __syncthreads();
    float s[NB];
#pragma unroll
    for (int b = 0; b < NB; b++) s[b] = 0.f;
#pragma unroll 4
    for (int a = ks; a < NADIM; a += 16) {
        float w = Wva[(size_t)a * ND + j];
#pragma unroll
        for (int b = 0; b < NB; b++) s[b] += ad_s[b * NADIM + a] * w;
    }
#pragma unroll
    for (int b = 0; b < NB; b++) red[ks][jj][b] = s[b];
    __syncthreads();
    if (tid < 64) {
        int j2 = tid & 7, b = tid >> 3;
        float t = 0.f;
#pragma unroll
        for (int k = 0; k < 16; k++) t += red[k][j2][b];
        tip[b * ND + blockIdx.x * 8 + j2] = t;
    }
}

__global__ void adapter2_kernel(const float* __restrict__ tip,
                                const float* __restrict__ Wo,
                                const float* __restrict__ bo,
                                float* __restrict__ bias)
{
    __shared__ float tip_s[NB * ND];
    __shared__ float red[16][8][NB];
    const int tid = threadIdx.x;
    const int jj = tid & 7, ks = tid >> 3;
    const int j = blockIdx.x * 8 + jj;
    for (int i = tid; i < NB * ND; i += 128) tip_s[i] = tip[i];
    __syncthreads();
    float s[NB];
#pragma unroll
    for (int b = 0; b < NB; b++) s[b] = 0.f;
#pragma unroll 4
    for (int kk = ks; kk < ND; kk += 16) {
        float w = Wo[(size_t)kk * ND + j];
#pragma unroll
        for (int b = 0; b < NB; b++) s[b] += tip_s[b * ND + kk] * w;
    }
#pragma unroll
    for (int b = 0; b < NB; b++) red[ks][jj][b] = s[b];
    __syncthreads();
    if (tid < 64) {
        int j2 = tid & 7, b = tid >> 3;
        float t = 0.f;
#pragma unroll
        for (int k = 0; k < 16; k++) t += red[k][j2][b];
        int col = blockIdx.x * 8 + j2;
        bias[b * ND + col] = bo[col] + t;
    }
}

// ---------------------------------------------------------------------------
extern "C" void kernel_launch(void* const* d_in, const int* in_sizes, int n_in,
                              void* d_out, int out_size)
{
    const float* hs  = (const float*)d_in[0];
    const float* enc = (const float*)d_in[1];
    const float* ad  = (const float*)d_in[2];
    const float* Wq  = (const float*)d_in[3];
    const float* Wk  = (const float*)d_in[4];
    const float* Wv  = (const float*)d_in[5];
    // d_in[6] = Wk_adapter: unused (softmax over a single key is identically 1)
    const float* Wva = (const float*)d_in[7];
    const float* Wo  = (const float*)d_in[8];
    const float* bo  = (const float*)d_in[9];
    float* out = (float*)d_out;

    __half *hs_h, *q, *attn_o, *enc_h, *kbuf, *vbuf, *wqt, *wot, *wkt, *wvt;
    float *tip, *bias, *kvpart;
    cudaGetSymbolAddress((void**)&hs_h,   g_hs_h);
    cudaGetSymbolAddress((void**)&q,      g_q);
    cudaGetSymbolAddress((void**)&attn_o, g_attn);
    cudaGetSymbolAddress((void**)&enc_h,  g_enc_h);
    cudaGetSymbolAddress((void**)&kbuf,   g_k);
    cudaGetSymbolAddress((void**)&vbuf,   g_v);
    cudaGetSymbolAddress((void**)&wqt,    g_wqt);
    cudaGetSymbolAddress((void**)&wot,    g_wot);
    cudaGetSymbolAddress((void**)&wkt,    g_wkt);
    cudaGetSymbolAddress((void**)&wvt,    g_wvt);
    cudaGetSymbolAddress((void**)&kvpart, g_kvpart);
    cudaGetSymbolAddress((void**)&tip,    g_tip);
    cudaGetSymbolAddress((void**)&bias,   g_bias);

    cudaFuncSetAttribute(h16_gemm<float>,  cudaFuncAttributeMaxDynamicSharedMemorySize, GEMM_SMEM);
    cudaFuncSetAttribute(h16_gemm<__half>, cudaFuncAttributeMaxDynamicSharedMemorySize, GEMM_SMEM);
    cudaFuncSetAttribute(kv_gemm,          cudaFuncAttributeMaxDynamicSharedMemorySize, GEMM_SMEM);
    cudaFuncSetAttribute(attn_mma_kernel,  cudaFuncAttributeMaxDynamicSharedMemorySize, ATTN_SMEM);

    long n4_hs  = (long)MQ * ND / 4;
    long n4_enc = (long)MKV_PAD * NCDIM / 4;
    long n4_all = n4_hs + n4_enc;

    // ncu captures launch index 3 -> Q-projection GEMM placed there
    f2h_all<<<(unsigned)((n4_all + 255) / 256), 256>>>(                                       // 0
        (const float4*)hs, (__half2*)hs_h, enc, enc_h, n4_hs, n4_enc);
    transpose_all_kernel<<<dim3(ND / 32, NCDIM / 32, 4), dim3(32, 8)>>>(                      // 1
        Wq, Wk, Wv, Wo, wqt, wkt, wvt, wot);
    adapter1_kernel<<<ND / 8, 128>>>(ad, Wva, tip);                                           // 2
    h16_gemm<__half><<<dim3(ND / 128, MQ / 128), 128, GEMM_SMEM>>>(                           // 3 (profiled)
        hs_h, wqt, q, MQ, ND, ND, nullptr, 1);

    // split-K KV projections (0.125 folded into wkt)
    kv_gemm<<<dim3(ND / 128, MKV_PAD / 128, 2 * KVSPLIT), 128, GEMM_SMEM>>>(
        enc_h, wkt, wvt, kvpart);
    {
        long r4 = (long)2 * MKV * ND / 4;
        kv_reduce<<<(unsigned)((r4 + 255) / 256), 256>>>(kvpart, kbuf, vbuf);
    }

    adapter2_kernel<<<ND / 8, 128>>>(tip, Wo, bo, bias);

    // persistent fp16 attention (8 q-tiles/CTA, cp.async Q streaming)
    attn_mma_kernel<<<dim3(NS / (128 * QT), NHEADS, NB), 256, ATTN_SMEM>>>(
        q, kbuf, vbuf, attn_o);

    // output projection + per-batch adapter bias (bo folded into bias), f32 out
    h16_gemm<float><<<dim3(ND / 128, MQ / 128), 128, GEMM_SMEM>>>(
        attn_o, wot, out, MQ, ND, ND, bias, NS);
}

// round 16
// speedup vs baseline: 1.2383x; 1.0554x over previous
#include <cuda_runtime.h>
#include <cuda_fp16.h>
#include <cstdint>
#include <math.h>

#define NB     8
#define NS     4096
#define ND     1280
#define NCTX   77
#define NKP    80          // padded keys
#define NCDIM  2048
#define NADIM  768
#define NHEADS 20
#define NHD    64
#define MQ     (NB*NS)     // 32768
#define MKV    616
#define MKV_PAD 640
#define KVSPLIT 4

// ---------------- scratch (device globals; no allocation allowed) -----------
__device__ __half g_hs_h[MQ * ND];           // fp16(hidden_states)
__device__ __half g_q[MQ * ND];              // Q projection (fp16)
__device__ __half g_attn[MQ * ND];           // attention out (fp16)
__device__ __half g_enc_h[MKV_PAD * NCDIM];  // fp16(encoder), padded rows
__device__ __half g_k[MKV * ND];             // K fp16 (0.125 folded into wkt)
__device__ __half g_v[MKV * ND];
__device__ __half g_wqt[ND * ND];            // W^T fp16  [N,K]
__device__ __half g_wot[ND * ND];
__device__ __half g_wkt[ND * NCDIM];         // includes 0.125 scale
__device__ __half g_wvt[ND * NCDIM];
__device__ float  g_kvpart[2 * KVSPLIT * MKV_PAD * ND];  // split-K partials
__device__ float  g_tip[NB * ND];
__device__ float  g_bias[NB * ND];

__device__ __forceinline__ void mma_f16(float* d, const uint32_t* a, const uint32_t* b) {
    asm volatile("mma.sync.aligned.m16n8k16.row.col.f32.f16.f16.f32 "
                 "{%0,%1,%2,%3}, {%4,%5,%6,%7}, {%8,%9}, {%0,%1,%2,%3};"
                 : "+f"(d[0]), "+f"(d[1]), "+f"(d[2]), "+f"(d[3])
                 : "r"(a[0]), "r"(a[1]), "r"(a[2]), "r"(a[3]),
                   "r"(b[0]), "r"(b[1]));
}
__device__ __forceinline__ void ldsm4(uint32_t* r, uint32_t addr) {
    asm volatile("ldmatrix.sync.aligned.m8n8.x4.shared.b16 {%0,%1,%2,%3}, [%4];"
                 : "=r"(r[0]), "=r"(r[1]), "=r"(r[2]), "=r"(r[3]) : "r"(addr));
}
__device__ __forceinline__ uint32_t pack_h2(float lo, float hi) {
    __half2 t = __floats2half2_rn(lo, hi);
    return *reinterpret_cast<uint32_t*>(&t);
}

// ---------------- shared GEMM core pieces ------------------------------------
#define BK 64
#define ATILE 16384                     // 128 rows x 128B
#define STAGE_BYTES (2 * ATILE)
#define GEMM_SMEM (2 * STAGE_BYTES)     // 64 KB

#define LOAD_STAGE(t) do {                                                    \
        uint32_t st_ = sbase + (uint32_t)((t) & 1) * STAGE_BYTES;             \
        int k0_ = (t) * BK;                                                   \
        _Pragma("unroll")                                                     \
        for (int i_ = 0; i_ < 8; i_++) {                                      \
            asm volatile("cp.async.cg.shared.global [%0], [%1], 16;"          \
                :: "r"(st_ + so0 + i_ * 2048u), "l"(gA0 + k0_ + i_ * gstep)); \
            asm volatile("cp.async.cg.shared.global [%0], [%1], 16;"          \
                :: "r"(st_ + ATILE + so0 + i_ * 2048u),                       \
                   "l"(gB0 + k0_ + i_ * gstep));                              \
        }                                                                     \
        asm volatile("cp.async.commit_group;" ::: "memory");                  \
    } while (0)

#define GEMM_BODY_MAIN()                                                      \
    const int g = lane >> 3, rin = lane & 7;                                  \
    const int ac = g >> 1;                                                    \
    uint32_t aoff[4], amask[4];                                               \
    _Pragma("unroll")                                                         \
    for (int mf = 0; mf < 4; mf++) {                                          \
        int ar = warp_m * 64 + mf * 16 + (g & 1) * 8 + rin;                   \
        aoff[mf] = (uint32_t)ar * 128;                                        \
        amask[mf] = (uint32_t)(ar & 7);                                       \
    }                                                                         \
    const int bc = g & 1;                                                     \
    uint32_t boff[4], bmask[4];                                               \
    _Pragma("unroll")                                                         \
    for (int p = 0; p < 4; p++) {                                             \
        int br = warp_n * 64 + (2 * p + (g >> 1)) * 8 + rin;                  \
        boff[p] = ATILE + (uint32_t)br * 128;                                 \
        bmask[p] = (uint32_t)(br & 7);                                        \
    }                                                                         \
    float acc[4][8][4];                                                       \
    _Pragma("unroll")                                                         \
    for (int mf = 0; mf < 4; mf++)                                            \
        _Pragma("unroll")                                                     \
        for (int nf = 0; nf < 8; nf++)                                        \
            _Pragma("unroll")                                                 \
            for (int j = 0; j < 4; j++) acc[mf][nf][j] = 0.f;                 \
    LOAD_STAGE(0);                                                            \
    LOAD_STAGE(1);                                                            \
    for (int s = 0; s < S; s++) {                                             \
        asm volatile("cp.async.wait_group %0;" :: "n"(1) : "memory");         \
        __syncthreads();                                                      \
        const uint32_t stg = sbase + (uint32_t)(s & 1) * STAGE_BYTES;         \
        _Pragma("unroll")                                                     \
        for (int kk = 0; kk < 4; kk++) {                                      \
            uint32_t bfr[4][4];                                               \
            _Pragma("unroll")                                                 \
            for (int p = 0; p < 4; p++)                                       \
                ldsm4(bfr[p], stg + boff[p] +                                 \
                      ((((uint32_t)(2 * kk + bc)) ^ bmask[p]) << 4));         \
            _Pragma("unroll")                                                 \
            for (int mf = 0; mf < 4; mf++) {                                  \
                uint32_t a[4];                                                \
                ldsm4(a, stg + aoff[mf] +                                     \
                      ((((uint32_t)(2 * kk + ac)) ^ amask[mf]) << 4));        \
                _Pragma("unroll")                                             \
                for (int nf = 0; nf < 8; nf++)                                \
                    mma_f16(acc[mf][nf], a, &bfr[nf >> 1][(nf & 1) * 2]);     \
            }                                                                 \
        }                                                                     \
        __syncthreads();                                                      \
        if (s + 2 < S) LOAD_STAGE(s + 2);                                     \
        else asm volatile("cp.async.commit_group;" ::: "memory");             \
    }

// ---------------- main fp16 GEMM (Q-proj / O-proj) ---------------------------
template <typename OutT>
__global__ __launch_bounds__(128, 3)
void h16_gemm(const __half* __restrict__ A, const __half* __restrict__ Bt,
              OutT* __restrict__ C, int M, int K, int Ntot,
              const float* __restrict__ bias, int rows_per_batch)
{
    extern __shared__ char smem[];
    const int tid = threadIdx.x;
    const int wid = tid >> 5, lane = tid & 31;
    const int warp_m = wid & 1;
    const int warp_n = wid >> 1;
    const int bm = blockIdx.y * 128;
    const int bn = blockIdx.x * 128;
    const int S = K / BK;
    const uint32_t sbase = (uint32_t)__cvta_generic_to_shared(smem);

    const int lrow = tid >> 3;
    const int lc16 = tid & 7;
    const __half* gA0 = A  + (size_t)(bm + lrow) * K + lc16 * 8;
    const __half* gB0 = Bt + (size_t)(bn + lrow) * K + lc16 * 8;
    const size_t gstep = (size_t)16 * K;
    const uint32_t so0 = (uint32_t)lrow * 128 + (uint32_t)((lc16 ^ (lrow & 7)) << 4);

    GEMM_BODY_MAIN()

#pragma unroll
    for (int mf = 0; mf < 4; mf++) {
        int r0 = bm + warp_m * 64 + mf * 16 + (lane >> 2);
#pragma unroll
        for (int half_ = 0; half_ < 2; half_++) {
            int r = r0 + half_ * 8;
            if (r >= M) continue;
            OutT* crow = C + (size_t)r * Ntot + bn + warp_n * 64;
            const float* brow = bias
                ? bias + (size_t)(r / rows_per_batch) * Ntot + bn + warp_n * 64
                : nullptr;
#pragma unroll
            for (int nf = 0; nf < 8; nf++) {
                int cc = nf * 8 + (lane & 3) * 2;
                float ox = acc[mf][nf][half_ * 2 + 0];
                float oy = acc[mf][nf][half_ * 2 + 1];
                if (bias) { ox += brow[cc]; oy += brow[cc + 1]; }
                if constexpr (sizeof(OutT) == 2) {
                    *(__half2*)(crow + cc) = __floats2half2_rn(ox, oy);
                } else {
                    *(float2*)(crow + cc) = make_float2(ox, oy);
                }
            }
        }
    }
}

// ---------------- split-K KV projection --------------------------------------
__global__ __launch_bounds__(128, 3)
void kv_gemm(const __half* __restrict__ enc_h, const __half* __restrict__ wkt,
             const __half* __restrict__ wvt, float* __restrict__ part)
{
    extern __shared__ char smem[];
    const int kv = blockIdx.z & 1;
    const int sp = blockIdx.z >> 1;                  // 0..KVSPLIT-1
    const int s_begin = sp * 8;
    const int S = 8;
    const __half* Bt = kv ? wvt : wkt;

    const int tid = threadIdx.x;
    const int wid = tid >> 5, lane = tid & 31;
    const int warp_m = wid & 1;
    const int warp_n = wid >> 1;
    const int bm = blockIdx.y * 128;
    const int bn = blockIdx.x * 128;
    const uint32_t sbase = (uint32_t)__cvta_generic_to_shared(smem);

    const int lrow = tid >> 3;
    const int lc16 = tid & 7;
    const __half* gA0 = enc_h + (size_t)(bm + lrow) * NCDIM + s_begin * BK + lc16 * 8;
    const __half* gB0 = Bt    + (size_t)(bn + lrow) * NCDIM + s_begin * BK + lc16 * 8;
    const size_t gstep = (size_t)16 * NCDIM;
    const uint32_t so0 = (uint32_t)lrow * 128 + (uint32_t)((lc16 ^ (lrow & 7)) << 4);

    GEMM_BODY_MAIN()

    float* base = part + ((size_t)(kv * KVSPLIT + sp)) * MKV_PAD * ND;
#pragma unroll
    for (int mf = 0; mf < 4; mf++) {
        int r0 = bm + warp_m * 64 + mf * 16 + (lane >> 2);
#pragma unroll
        for (int half_ = 0; half_ < 2; half_++) {
            int r = r0 + half_ * 8;
            float* crow = base + (size_t)r * ND + bn + warp_n * 64;
#pragma unroll
            for (int nf = 0; nf < 8; nf++) {
                int cc = nf * 8 + (lane & 3) * 2;
                *(float2*)(crow + cc) =
                    make_float2(acc[mf][nf][half_ * 2 + 0],
                                acc[mf][nf][half_ * 2 + 1]);
            }
        }
    }
}

// sum the split partials -> fp16 K/V buffers
__global__ void kv_reduce(const float* __restrict__ part,
                          __half* __restrict__ kbuf, __half* __restrict__ vbuf)
{
    long i = (long)blockIdx.x * blockDim.x + threadIdx.x;
    const long n4 = (long)2 * MKV * ND / 4;
    if (i >= n4) return;
    long e = i * 4;
    int kv = (int)(e / ((long)MKV * ND));
    long rem = e - (long)kv * MKV * ND;
    const float* b = part + (size_t)kv * KVSPLIT * MKV_PAD * ND + rem;
    float4 p0 = *(const float4*)(b);
    float4 p1 = *(const float4*)(b + (size_t)MKV_PAD * ND);
    float4 p2 = *(const float4*)(b + (size_t)2 * MKV_PAD * ND);
    float4 p3 = *(const float4*)(b + (size_t)3 * MKV_PAD * ND);
    __half* o = (kv ? vbuf : kbuf) + rem;
    *(__half2*)(o)     = __floats2half2_rn((p0.x + p1.x) + (p2.x + p3.x),
                                           (p0.y + p1.y) + (p2.y + p3.y));
    *(__half2*)(o + 2) = __floats2half2_rn((p0.z + p1.z) + (p2.z + p3.z),
                                           (p0.w + p1.w) + (p2.w + p3.w));
}

// ---------------- persistent attention: 8 q-tiles per CTA --------------------
#define QT 8
#define VPITCH 88
#define A_QS 0
#define A_KS (2 * 128 * 64)                   // 16384 (after Q double buffer)
#define A_VT (A_KS + NKP * 64)                // 21504
#define ATTN_SMEM ((A_VT + 64 * VPITCH) * 2)  // 54272 B

__global__ __launch_bounds__(256, 2)
void attn_mma_kernel(const __half* __restrict__ q, const __half* __restrict__ kbuf,
                     const __half* __restrict__ vbuf, __half* __restrict__ out)
{
    extern __shared__ __half smh[];
    __half* Qs = smh + A_QS;          // [2][128*64]
    __half* Ks = smh + A_KS;
    __half* Vt = smh + A_VT;

    const int b = blockIdx.z;
    const int h = blockIdx.y;
    const int qc0 = blockIdx.x * (QT * 128);
    const int tid = threadIdx.x;
    const int warp = tid >> 5, lane = tid & 31;
    const int rb = lane >> 2, cb = lane & 3;

    // per-thread Q prefetch addressing: 4 chunks of 16B
    const uint32_t sbase = (uint32_t)__cvta_generic_to_shared(smh);
    uint32_t qdst[4];
    const __half* qsrc[4];
#pragma unroll
    for (int j = 0; j < 4; j++) {
        int idx = tid + j * 256;          // 0..1023
        int r = idx >> 3, c = idx & 7;
        qdst[j] = sbase + 2u * ((uint32_t)r * 64 + ((c ^ (r & 7)) << 3));
        qsrc[j] = q + ((size_t)(b * NS + qc0 + r)) * ND + h * NHD + c * 8;
    }
#define Q_PREFETCH(t) do {                                                    \
        uint32_t bufo = (uint32_t)((t) & 1) * 16384u;                         \
        _Pragma("unroll")                                                     \
        for (int j_ = 0; j_ < 4; j_++)                                        \
            asm volatile("cp.async.cg.shared.global [%0], [%1], 16;"          \
                :: "r"(qdst[j_] + bufo),                                      \
                   "l"(qsrc[j_] + (size_t)(t) * 128 * ND));                   \
        asm volatile("cp.async.commit_group;" ::: "memory");                  \
    } while (0)

    // prefetch first Q tile before the K/V fills so it overlaps them
    Q_PREFETCH(0);

    // K/V fills (once per CTA)
    for (int i = tid; i < NKP * 8; i += 256) {
        int r = i >> 3, c = i & 7;
        uint4 t = make_uint4(0u, 0u, 0u, 0u);
        if (r < NCTX)
            t = *(const uint4*)&kbuf[((size_t)(b * NCTX + r)) * ND + h * NHD + c * 8];
        *(uint4*)&Ks[r * 64 + ((c ^ (r & 7)) << 3)] = t;
    }
    for (int i = tid; i < NKP * NHD; i += 256) {
        int r = i >> 6, d = i & 63;
        __half t = (r < NCTX)
            ? vbuf[((size_t)(b * NCTX + r)) * ND + h * NHD + d] : __half(0.f);
        Vt[d * VPITCH + r] = t;
    }

    const int qrow = warp * 16 + rb;

    for (int t = 0; t < QT; t++) {
        if (t + 1 < QT) {
            Q_PREFETCH(t + 1);
            asm volatile("cp.async.wait_group 1;" ::: "memory");
        } else {
            asm volatile("cp.async.wait_group 0;" ::: "memory");
        }
        __syncthreads();   // tile t visible (also covers K/V STS on t=0)

        const __half* Qb = Qs + (t & 1) * (128 * 64);
        const int q0 = qc0 + t * 128;

        // ---- S = Q K^T ----
        float sacc[10][4];
#pragma unroll
        for (int nf = 0; nf < 10; nf++)
#pragma unroll
            for (int j = 0; j < 4; j++) sacc[nf][j] = 0.f;

#pragma unroll
        for (int kk = 0; kk < 4; kk++) {
            uint32_t a[4];
            {
                uint32_t a0 = (uint32_t)qrow * 128 + (((2 * kk) ^ rb) << 4) + cb * 4;
                const char* base = (const char*)Qb;
                a[0] = *(const uint32_t*)(base + a0);
                a[1] = *(const uint32_t*)(base + a0 + 1024);
                a[2] = *(const uint32_t*)(base + (a0 ^ 16));
                a[3] = *(const uint32_t*)(base + ((a0 + 1024) ^ 16));
            }
#pragma unroll
            for (int nf = 0; nf < 10; nf++) {
                int n = nf * 8 + rb;
                uint32_t b0 = (uint32_t)n * 128 + (((2 * kk) ^ rb) << 4) + cb * 4;
                const char* base = (const char*)Ks;
                uint32_t bf[2];
                bf[0] = *(const uint32_t*)(base + b0);
                bf[1] = *(const uint32_t*)(base + (b0 ^ 16));
                mma_f16(sacc[nf], a, bf);
            }
        }

        // mask padded keys (cols 77..79 in nf=9)
        if (2 * cb >= 5)     { sacc[9][0] = -1e30f; sacc[9][2] = -1e30f; }
        if (2 * cb + 1 >= 5) { sacc[9][1] = -1e30f; sacc[9][3] = -1e30f; }

        // ---- softmax (register-resident P) ----
        float m0 = -1e30f, m1 = -1e30f;
#pragma unroll
        for (int nf = 0; nf < 10; nf++) {
            m0 = fmaxf(m0, fmaxf(sacc[nf][0], sacc[nf][1]));
            m1 = fmaxf(m1, fmaxf(sacc[nf][2], sacc[nf][3]));
        }
        m0 = fmaxf(m0, __shfl_xor_sync(0xFFFFFFFF, m0, 1));
        m0 = fmaxf(m0, __shfl_xor_sync(0xFFFFFFFF, m0, 2));
        m1 = fmaxf(m1, __shfl_xor_sync(0xFFFFFFFF, m1, 1));
        m1 = fmaxf(m1, __shfl_xor_sync(0xFFFFFFFF, m1, 2));

        float l0 = 0.f, l1 = 0.f;
        uint32_t pfrag[10][2];
#pragma unroll
        for (int nf = 0; nf < 10; nf++) {
            float p0 = __expf(sacc[nf][0] - m0);
            float p1 = __expf(sacc[nf][1] - m0);
            float p2 = __expf(sacc[nf][2] - m1);
            float p3 = __expf(sacc[nf][3] - m1);
            l0 += p0 + p1; l1 += p2 + p3;
            pfrag[nf][0] = pack_h2(p0, p1);
            pfrag[nf][1] = pack_h2(p2, p3);
        }
        l0 += __shfl_xor_sync(0xFFFFFFFF, l0, 1);
        l0 += __shfl_xor_sync(0xFFFFFFFF, l0, 2);
        l1 += __shfl_xor_sync(0xFFFFFFFF, l1, 1);
        l1 += __shfl_xor_sync(0xFFFFFFFF, l1, 2);

        // ---- O = P · Vt^T ----
        float oacc[8][4];
#pragma unroll
        for (int nf = 0; nf < 8; nf++)
#pragma unroll
            for (int j = 0; j < 4; j++) oacc[nf][j] = 0.f;

#pragma unroll
        for (int kk = 0; kk < 5; kk++) {
            uint32_t a[4];
            a[0] = pfrag[2 * kk][0];
            a[1] = pfrag[2 * kk][1];
            a[2] = pfrag[2 * kk + 1][0];
            a[3] = pfrag[2 * kk + 1][1];
#pragma unroll
            for (int nf = 0; nf < 8; nf++) {
                int n = nf * 8 + rb;
                uint32_t bf[2];
                bf[0] = *(const uint32_t*)&Vt[n * VPITCH + kk * 16 + 2 * cb];
                bf[1] = *(const uint32_t*)&Vt[n * VPITCH + kk * 16 + 8 + 2 * cb];
                mma_f16(oacc[nf], a, bf);
            }
        }

        const float inv0 = 1.f / l0, inv1 = 1.f / l1;
        __half* o0 = &out[((size_t)(b * NS + q0 + qrow)) * ND + h * NHD];
        __half* o1 = o0 + (size_t)8 * ND;
#pragma unroll
        for (int nf = 0; nf < 8; nf++) {
            int cc = nf * 8 + 2 * cb;
            *(__half2*)(o0 + cc) = __floats2half2_rn(oacc[nf][0] * inv0, oacc[nf][1] * inv0);
            *(__half2*)(o1 + cc) = __floats2half2_rn(oacc[nf][2] * inv1, oacc[nf][3] * inv1);
        }

        __syncthreads();   // all reads of Qs[t&1] done before its next overwrite
    }
#undef Q_PREFETCH
}

// ---------------- preprocessing: hs + enc fp32->fp16 in one launch -----------
__global__ void f2h_all(const float4* __restrict__ hs, __half2* __restrict__ hs_out,
                        const float* __restrict__ enc, __half* __restrict__ enc_out,
                        long n4_hs, long n4_enc)
{
    long i = (long)blockIdx.x * blockDim.x + threadIdx.x;
    if (i < n4_hs) {
        float4 v = hs[i];
        hs_out[i * 2]     = __floats2half2_rn(v.x, v.y);
        hs_out[i * 2 + 1] = __floats2half2_rn(v.z, v.w);
    } else {
        long j = i - n4_hs;
        if (j < n4_enc) {
            long e = j * 4;
            long row = e / NCDIM;
            if (row < MKV) {
                float4 v = *(const float4*)(enc + e);
                *(__half2*)(enc_out + e)     = __floats2half2_rn(v.x, v.y);
                *(__half2*)(enc_out + e + 2) = __floats2half2_rn(v.z, v.w);
            } else {
                *(__half2*)(enc_out + e)     = __floats2half2_rn(0.f, 0.f);
                *(__half2*)(enc_out + e + 2) = __floats2half2_rn(0.f, 0.f);
            }
        }
    }
}

// all four weight transposes in one launch (z selects the matrix)
__global__ void transpose_all_kernel(const float* __restrict__ Wq, const float* __restrict__ Wk,
                                     const float* __restrict__ Wv, const float* __restrict__ Wo,
                                     __half* __restrict__ wqt, __half* __restrict__ wkt,
                                     __half* __restrict__ wvt, __half* __restrict__ wot)
{
    const float* W; __half* Wt; int K; float scale = 1.f;
    switch (blockIdx.z) {
        case 0:  W = Wq; Wt = wqt; K = ND;    break;
        case 1:  W = Wk; Wt = wkt; K = NCDIM; scale = 0.125f; break;
        case 2:  W = Wv; Wt = wvt; K = NCDIM; break;
        default: W = Wo; Wt = wot; K = ND;    break;
    }
    int k0 = blockIdx.y * 32, n0 = blockIdx.x * 32;
    if (k0 >= K) return;
    __shared__ float t[32][33];
    int x = threadIdx.x, y = threadIdx.y;
#pragma unroll
    for (int i = 0; i < 32; i += 8)
        t[y + i][x] = W[(size_t)(k0 + y + i) * ND + n0 + x];
    __syncthreads();
#pragma unroll
    for (int i = 0; i < 32; i += 8)
        Wt[(size_t)(n0 + y + i) * K + k0 + x] = __float2half_rn(t[x][y + i] * scale);
}

// ---------------- adapter branch (batch-shared weight reads) ----------------
__global__ void adapter1_kernel(const float* __restrict__ ad,
                                const float* __restrict__ Wva,
                                float* __restrict__ tip)
{
    __shared__ float ad_s[NB * NADIM];
    __shared__ float red[16][8][NB];
    const int tid = threadIdx.x;
    const int jj = tid & 7, ks = tid >> 3;
    const int j = blockIdx.x * 8 + jj;
    for (int i = tid; i < NB * NADIM; i += 128) ad_s[i] = ad[i];
    __syncthreads();
    float s[NB];
#pragma unroll
    for (int b = 0; b < NB; b++) s[b] = 0.f;
#pragma unroll 4
    for (int a = ks; a < NADIM; a += 16) {
        float w = Wva[(size_t)a * ND + j];
#pragma unroll
        for (int b = 0; b < NB; b++) s[b] += ad_s[b * NADIM + a] * w;
    }
#pragma unroll
    for (int b = 0; b < NB; b++) red[ks][jj][b] = s[b];
    __syncthreads();
    if (tid < 64) {
        int j2 = tid & 7, b = tid >> 3;
        float t = 0.f;
#pragma unroll
        for (int k = 0; k < 16; k++) t += red[k][j2][b];
        tip[b * ND + blockIdx.x * 8 + j2] = t;
    }
}

__global__ void adapter2_kernel(const float* __restrict__ tip,
                                const float* __restrict__ Wo,
                                const float* __restrict__ bo,
                                float* __restrict__ bias)
{
    __shared__ float tip_s[NB * ND];
    __shared__ float red[16][8][NB];
    const int tid = threadIdx.x;
    const int jj = tid & 7, ks = tid >> 3;
    const int j = blockIdx.x * 8 + jj;
    for (int i = tid; i < NB * ND; i += 128) tip_s[i] = tip[i];
    __syncthreads();
    float s[NB];
#pragma unroll
    for (int b = 0; b < NB; b++) s[b] = 0.f;
#pragma unroll 4
    for (int kk = ks; kk < ND; kk += 16) {
        float w = Wo[(size_t)kk * ND + j];
#pragma unroll
        for (int b = 0; b < NB; b++) s[b] += tip_s[b * ND + kk] * w;
    }
#pragma unroll
    for (int b = 0; b < NB; b++) red[ks][jj][b] = s[b];
    __syncthreads();
    if (tid < 64) {
        int j2 = tid & 7, b = tid >> 3;
        float t = 0.f;
#pragma unroll
        for (int k = 0; k < 16; k++) t += red[k][j2][b];
        int col = blockIdx.x * 8 + j2;
        bias[b * ND + col] = bo[col] + t;
    }
}

// ---------------------------------------------------------------------------
extern "C" void kernel_launch(void* const* d_in, const int* in_sizes, int n_in,
                              void* d_out, int out_size)
{
    const float* hs  = (const float*)d_in[0];
    const float* enc = (const float*)d_in[1];
    const float* ad  = (const float*)d_in[2];
    const float* Wq  = (const float*)d_in[3];
    const float* Wk  = (const float*)d_in[4];
    const float* Wv  = (const float*)d_in[5];
    // d_in[6] = Wk_adapter: unused (softmax over a single key is identically 1)
    const float* Wva = (const float*)d_in[7];
    const float* Wo  = (const float*)d_in[8];
    const float* bo  = (const float*)d_in[9];
    float* out = (float*)d_out;

    __half *hs_h, *q, *attn_o, *enc_h, *kbuf, *vbuf, *wqt, *wot, *wkt, *wvt;
    float *tip, *bias, *kvpart;
    cudaGetSymbolAddress((void**)&hs_h,   g_hs_h);
    cudaGetSymbolAddress((void**)&q,      g_q);
    cudaGetSymbolAddress((void**)&attn_o, g_attn);
    cudaGetSymbolAddress((void**)&enc_h,  g_enc_h);
    cudaGetSymbolAddress((void**)&kbuf,   g_k);
    cudaGetSymbolAddress((void**)&vbuf,   g_v);
    cudaGetSymbolAddress((void**)&wqt,    g_wqt);
    cudaGetSymbolAddress((void**)&wot,    g_wot);
    cudaGetSymbolAddress((void**)&wkt,    g_wkt);
    cudaGetSymbolAddress((void**)&wvt,    g_wvt);
    cudaGetSymbolAddress((void**)&kvpart, g_kvpart);
    cudaGetSymbolAddress((void**)&tip,    g_tip);
    cudaGetSymbolAddress((void**)&bias,   g_bias);

    cudaFuncSetAttribute(h16_gemm<float>,  cudaFuncAttributeMaxDynamicSharedMemorySize, GEMM_SMEM);
    cudaFuncSetAttribute(h16_gemm<__half>, cudaFuncAttributeMaxDynamicSharedMemorySize, GEMM_SMEM);
    cudaFuncSetAttribute(kv_gemm,          cudaFuncAttributeMaxDynamicSharedMemorySize, GEMM_SMEM);
    cudaFuncSetAttribute(attn_mma_kernel,  cudaFuncAttributeMaxDynamicSharedMemorySize, ATTN_SMEM);

    long n4_hs  = (long)MQ * ND / 4;
    long n4_enc = (long)MKV_PAD * NCDIM / 4;
    long n4_all = n4_hs + n4_enc;

    // side stream + events (host-side objects; leaked deliberately — destroying
    // a stream that participated in an active capture invalidates the capture)
    cudaStream_t s2;
    cudaStreamCreateWithFlags(&s2, cudaStreamNonBlocking);
    cudaEvent_t e0, e_kv, e_bias;
    cudaEventCreateWithFlags(&e0,     cudaEventDisableTiming);
    cudaEventCreateWithFlags(&e_kv,   cudaEventDisableTiming);
    cudaEventCreateWithFlags(&e_bias, cudaEventDisableTiming);

    // ---- main stream: preprocessing shared by both chains ----
    f2h_all<<<(unsigned)((n4_all + 255) / 256), 256>>>(
        (const float4*)hs, (__half2*)hs_h, enc, enc_h, n4_hs, n4_enc);
    transpose_all_kernel<<<dim3(ND / 32, NCDIM / 32, 4), dim3(32, 8)>>>(
        Wq, Wk, Wv, Wo, wqt, wkt, wvt, wot);
    cudaEventRecord(e0, 0);

    // ---- side stream: KV projections + adapter bias (overlap Q-proj) ----
    cudaStreamWaitEvent(s2, e0, 0);
    kv_gemm<<<dim3(ND / 128, MKV_PAD / 128, 2 * KVSPLIT), 128, GEMM_SMEM, s2>>>(
        enc_h, wkt, wvt, kvpart);
    {
        long r4 = (long)2 * MKV * ND / 4;
        kv_reduce<<<(unsigned)((r4 + 255) / 256), 256, 0, s2>>>(kvpart, kbuf, vbuf);
    }
    cudaEventRecord(e_kv, s2);
    adapter1_kernel<<<ND / 8, 128, 0, s2>>>(ad, Wva, tip);
    adapter2_kernel<<<ND / 8, 128, 0, s2>>>(tip, Wo, bo, bias);
    cudaEventRecord(e_bias, s2);

    // ---- main stream: Q-proj (runs concurrently with the side chain) ----
    h16_gemm<__half><<<dim3(ND / 128, MQ / 128), 128, GEMM_SMEM>>>(
        hs_h, wqt, q, MQ, ND, ND, nullptr, 1);

    // attention needs kbuf/vbuf from the side chain
    cudaStreamWaitEvent(0, e_kv, 0);
    attn_mma_kernel<<<dim3(NS / (128 * QT), NHEADS, NB), 256, ATTN_SMEM>>>(
        q, kbuf, vbuf, attn_o);

    // O-proj needs the adapter bias
    cudaStreamWaitEvent(0, e_bias, 0);
    h16_gemm<float><<<dim3(ND / 128, MQ / 128), 128, GEMM_SMEM>>>(
        attn_o, wot, out, MQ, ND, ND, bias, NS);
}